// round 5
// baseline (speedup 1.0000x reference)
#include <cuda_runtime.h>
#include <cstdint>
#include <float.h>
#include <math.h>

// ---------------------------------------------------------------------------
// TS2Vec hierarchical loss, B=8, T=2048, C=64, ALPHA=0.5, TAU=0.1, EPS=1e-5
// Round 5: Gram via mma.sync tf32 (split hi/lo, 3 passes), reg accumulators.
// (Round-4 fix: cvt.rna.tf32.f32 needs .b32 destination register.)
// ---------------------------------------------------------------------------

#define TTOP 2048
#define CDIM 64

__device__ double g_acc;
__device__ __align__(16) float g_pyr[2][8 * 2047 * 64];   // pooled levels 1..11
__device__ float g_row_m[4094 * 16];                       // per-row online max
__device__ float g_row_d[4094 * 16];                       // per-row online denom

__device__ __forceinline__ int pyrOff(int l) { return 512 * (2048 - (4096 >> l)); }
__device__ __forceinline__ int rowOff(int l) { return 4096 - (4096 >> l); }
__device__ __forceinline__ const float* lvl_base(int l, int b,
                                                 const float* z1, const float* z2) {
    int bb = b & 7;
    const float* z = (b < 8) ? z1 : z2;
    const float* p = (b < 8) ? g_pyr[0] : g_pyr[1];
    if (l == 0) return z + (size_t)bb * TTOP * CDIM;
    return p + pyrOff(l) + (size_t)bb * (size_t)(TTOP >> l) * CDIM;
}

// tf32 round: destination of cvt.rna.tf32.f32 is a .b32 register.
__device__ __forceinline__ float tf32r(float x) {
    uint32_t r;
    asm("cvt.rna.tf32.f32 %0, %1;" : "=r"(r) : "f"(x));
    return __uint_as_float(r);
}

__device__ __forceinline__ void mma_tf32(float c[4], uint32_t a0, uint32_t a1,
                                         uint32_t a2, uint32_t a3,
                                         uint32_t b0, uint32_t b1) {
    asm volatile(
        "mma.sync.aligned.m16n8k8.row.col.f32.tf32.tf32.f32 "
        "{%0,%1,%2,%3}, {%4,%5,%6,%7}, {%8,%9}, {%0,%1,%2,%3};"
        : "+f"(c[0]), "+f"(c[1]), "+f"(c[2]), "+f"(c[3])
        : "r"(a0), "r"(a1), "r"(a2), "r"(a3), "r"(b0), "r"(b1));
}

// ---------------------------------------------------------------------------
__global__ void k_init() { g_acc = 0.0; }

__global__ void k_poolA(const float* __restrict__ z1, const float* __restrict__ z2) {
    int idx = blockIdx.x * blockDim.x + threadIdx.x;
    const int NPER = 512 * 2016;
    if (idx >= 2 * NPER) return;
    int tensor = (idx >= NPER) ? 1 : 0;
    int off = idx - tensor * NPER;
    const float* in = tensor ? z2 : z1;
    int l = 1, T = 1024;
    while (off >= 512 * T) { off -= 512 * T; ++l; T >>= 1; }
    int c = off & 63;
    int t = (off >> 6) % T;
    int b = (off >> 6) / T;
    int w = TTOP / T;
    const float* src = in + ((size_t)b * TTOP + (size_t)t * w) * CDIM + c;
    float m = src[0];
    for (int k = 1; k < w; k++) m = fmaxf(m, src[(size_t)k * CDIM]);
    g_pyr[tensor][pyrOff(l) + ((size_t)b * T + t) * CDIM + c] = m;
}

__global__ void k_poolB() {
    int idx = blockIdx.x * blockDim.x + threadIdx.x;
    const int NPER = 512 * 31;
    if (idx >= 2 * NPER) return;
    int tensor = (idx >= NPER) ? 1 : 0;
    int off = idx - tensor * NPER;
    int l = 7, T = 16;
    while (off >= 512 * T) { off -= 512 * T; ++l; T >>= 1; }
    int c = off & 63;
    int t = (off >> 6) % T;
    int b = (off >> 6) / T;
    int w = 32 / T;
    const float* src = g_pyr[tensor] + pyrOff(6) + ((size_t)b * 32 + (size_t)t * w) * CDIM + c;
    float m = src[0];
    for (int k = 1; k < w; k++) m = fmaxf(m, src[(size_t)k * CDIM]);
    g_pyr[tensor][pyrOff(l) + ((size_t)b * T + t) * CDIM + c] = m;
}

// ---------------------------------------------------------------------------
// Instance loss: warp-per-slice. 512 blocks x 8 warps = 4096 >= 4095 slices.
__global__ void __launch_bounds__(256)
k_inst(const float* __restrict__ z1, const float* __restrict__ z2) {
    __shared__ float zs[8][16][68];
    __shared__ float sim[8][16][17];
    __shared__ double wres[8];
    int tid = threadIdx.x;
    int w = tid >> 5, lid = tid & 31;
    int slice = blockIdx.x * 8 + w;
    double myres = 0.0;

    if (slice < 4095) {
        int l = 0, T = TTOP, t = slice;
        while (t >= T) { t -= T; ++l; T >>= 1; }

#pragma unroll
        for (int q = 0; q < 8; q++) {
            int e = lid + q * 32;
            int r = e >> 4, c4 = e & 15;
            const float* rowp = lvl_base(l, r, z1, z2) + (size_t)t * CDIM;
            *reinterpret_cast<float4*>(&zs[w][r][4 * c4]) =
                *reinterpret_cast<const float4*>(rowp + 4 * c4);
        }
        __syncwarp();

        int i = lid >> 1;
        int jb = (lid & 1) << 3;
#pragma unroll
        for (int q = 0; q < 8; q++) {
            int j = jb + q;
            float acc = 0.f;
#pragma unroll
            for (int k4 = 0; k4 < 16; k4++) {
                float4 a = *reinterpret_cast<const float4*>(&zs[w][i][4 * k4]);
                float4 b = *reinterpret_cast<const float4*>(&zs[w][j][4 * k4]);
                acc += a.x * b.x + a.y * b.y + a.z * b.z + a.w * b.w;
            }
            sim[w][i][j] = acc;
        }
        __syncwarp();

        float v = 0.f;
        if (lid < 16) {
            float m = -FLT_MAX;
#pragma unroll
            for (int jj = 0; jj < 16; jj++)
                if (jj != lid) m = fmaxf(m, sim[w][lid][jj]);
            float s = 0.f;
#pragma unroll
            for (int jj = 0; jj < 16; jj++)
                if (jj != lid) s += expf(sim[w][lid][jj] - m);
            int pos = (lid < 8) ? lid + 8 : lid - 8;
            v = m + logf(s) - sim[w][lid][pos];
        }
#pragma unroll
        for (int o = 16; o > 0; o >>= 1) v += __shfl_down_sync(0xffffffffu, v, o);
        if (lid == 0) myres = (double)v / (384.0 * (double)T);
    }
    if (lid == 0) wres[w] = myres;
    __syncthreads();
    if (tid == 0) {
        double tot = 0.0;
#pragma unroll
        for (int q = 0; q < 8; q++) tot += wres[q];
        atomicAdd(&g_acc, tot);
    }
}

// ---------------------------------------------------------------------------
// Temporal kernel A.
// Smem tile layout (per tile): 128 rows, each row = 8 ksteps x 4 pairs of
// float2 {z[8s+c], z[8s+c+4]}, row stride 36 float2 (288B) for conflict-free
// half-warp fragment fetches.
#define TS 128
#define ROWF2 36
#define TILEF2 (128 * ROWF2)                        // float2 per tile
#define TA_DYN_SMEM (4 * TILEF2 * 8)                // bytes

__device__ __forceinline__ void load_split(float2* hi, float2* lo,
                                           const float* zb, int r0, int T,
                                           int tid) {
#pragma unroll
    for (int it = 0; it < 4; it++) {
        int e = tid + it * 256;                     // 0..1023 = (r, s)
        int r = e >> 3, s = e & 7;
        float4 a = make_float4(0.f, 0.f, 0.f, 0.f);
        float4 b = make_float4(0.f, 0.f, 0.f, 0.f);
        if (r0 + r < T) {
            const float* src = zb + (size_t)(r0 + r) * CDIM + 8 * s;
            a = *reinterpret_cast<const float4*>(src);
            b = *reinterpret_cast<const float4*>(src + 4);
        }
        float hax = tf32r(a.x), hay = tf32r(a.y), haz = tf32r(a.z), haw = tf32r(a.w);
        float hbx = tf32r(b.x), hby = tf32r(b.y), hbz = tf32r(b.z), hbw = tf32r(b.w);
        float lax = tf32r(a.x - hax), lay = tf32r(a.y - hay);
        float laz = tf32r(a.z - haz), law = tf32r(a.w - haw);
        float lbx = tf32r(b.x - hbx), lby = tf32r(b.y - hby);
        float lbz = tf32r(b.z - hbz), lbw = tf32r(b.w - hbw);
        float2* ph = hi + r * ROWF2 + s * 4;
        float2* pl = lo + r * ROWF2 + s * 4;
        *reinterpret_cast<float4*>(ph)     = make_float4(hax, hbx, hay, hby);
        *reinterpret_cast<float4*>(ph + 2) = make_float4(haz, hbz, haw, hbw);
        *reinterpret_cast<float4*>(pl)     = make_float4(lax, lbx, lay, lby);
        *reinterpret_cast<float4*>(pl + 2) = make_float4(laz, lbz, law, lbw);
    }
}

__device__ __forceinline__ void gemm_pass(float acc[4][4][4],
                                          const float2* __restrict__ A,
                                          const float2* __restrict__ B,
                                          int wm, int wn, int g, int t) {
#pragma unroll
    for (int s = 0; s < 8; s++) {
        uint32_t a[4][4];
#pragma unroll
        for (int mf = 0; mf < 4; mf++) {
            int row = wm * 64 + mf * 16 + g;
            float2 fa = A[row * ROWF2 + s * 4 + t];
            float2 fb = A[(row + 8) * ROWF2 + s * 4 + t];
            a[mf][0] = __float_as_uint(fa.x);
            a[mf][2] = __float_as_uint(fa.y);
            a[mf][1] = __float_as_uint(fb.x);
            a[mf][3] = __float_as_uint(fb.y);
        }
        uint32_t bb[4][2];
#pragma unroll
        for (int nf = 0; nf < 4; nf++) {
            int row = wn * 32 + nf * 8 + g;
            float2 f = B[row * ROWF2 + s * 4 + t];
            bb[nf][0] = __float_as_uint(f.x);
            bb[nf][1] = __float_as_uint(f.y);
        }
#pragma unroll
        for (int mf = 0; mf < 4; mf++)
#pragma unroll
            for (int nf = 0; nf < 4; nf++)
                mma_tf32(acc[mf][nf], a[mf][0], a[mf][1], a[mf][2], a[mf][3],
                         bb[nf][0], bb[nf][1]);
    }
}

__device__ __forceinline__ void upd(float v, float& m, float& d, float& tsum) {
    float s = v * 10.0f;
    tsum += s;
    if (s > m) { d = d * __expf(m - s) + 1.0f; m = s; }
    else if (s > m - 60.0f) d += __expf(s - m);
}

__global__ void __launch_bounds__(256, 1)
k_tempA(const float* __restrict__ z1, const float* __restrict__ z2) {
    extern __shared__ float2 dsm2[];
    float2* xh = dsm2;
    float2* xl = xh + TILEF2;
    float2* yh = xl + TILEF2;
    float2* yl = yh + TILEF2;
    __shared__ float red_m[128][16];
    __shared__ float red_d[128][16];
    __shared__ double wsum[8];

    int tid = threadIdx.x;
    int wid = tid >> 5, lid = tid & 31;
    int wm = wid >> 2, wn = wid & 3;                // 2 x 4 warp grid
    int g = lid >> 2, t = lid & 3;

    // decode block -> (level, b, xtile pair)
    int bid = blockIdx.x;
    int l = 0, T = TTOP, npair;
    for (;;) {
        int nt = (T + TS - 1) / TS; if (nt < 1) nt = 1;
        npair = (nt + 1) >> 1;
        int cnt = 16 * npair;
        if (bid < cnt) break;
        bid -= cnt; ++l; T >>= 1;
        if (l > 10) return;
    }
    int NT = (T + TS - 1) / TS; if (NT < 1) NT = 1;
    int b = bid / npair;
    int p = bid % npair;
    const float* zb = lvl_base(l, b, z1, z2);

    int xtiles[2];
    int nxt = 1;
    xtiles[0] = p;
    if (NT - 1 - p != p) { xtiles[1] = NT - 1 - p; nxt = 2; }

    double Ssum = 0.0;

    for (int xi = 0; xi < nxt; xi++) {
        int xt = xtiles[xi];
        int x0 = xt * TS;
        __syncthreads();                            // smem reuse guard
        load_split(xh, xl, zb, x0, T, tid);

        float m[8], d[8];
#pragma unroll
        for (int q = 0; q < 8; q++) { m[q] = -FLT_MAX; d[q] = 0.f; }

        for (int yt = xt; yt < NT; yt++) {
            int y0 = yt * TS;
            __syncthreads();                        // prev reads done
            load_split(yh, yl, zb, y0, T, tid);
            __syncthreads();                        // tiles ready

            float acc[4][4][4];
#pragma unroll
            for (int mf = 0; mf < 4; mf++)
#pragma unroll
                for (int nf = 0; nf < 4; nf++)
#pragma unroll
                    for (int q = 0; q < 4; q++) acc[mf][nf][q] = 0.f;

            gemm_pass(acc, xh, yh, wm, wn, g, t);
            gemm_pass(acc, xh, yl, wm, wn, g, t);
            gemm_pass(acc, xl, yh, wm, wn, g, t);

            float tsum = 0.f;
#pragma unroll
            for (int mf = 0; mf < 4; mf++) {
                int xr = x0 + wm * 64 + mf * 16 + g;
                int xr2 = xr + 8;
#pragma unroll
                for (int nf = 0; nf < 4; nf++) {
                    int yc = y0 + wn * 32 + nf * 8 + 2 * t;
                    float* a = acc[mf][nf];
                    if (xr < T) {
                        if (yc < T && yc > xr)      upd(a[0], m[2*mf],   d[2*mf],   tsum);
                        if (yc + 1 < T && yc + 1 > xr) upd(a[1], m[2*mf], d[2*mf], tsum);
                    }
                    if (xr2 < T) {
                        if (yc < T && yc > xr2)     upd(a[2], m[2*mf+1], d[2*mf+1], tsum);
                        if (yc + 1 < T && yc + 1 > xr2) upd(a[3], m[2*mf+1], d[2*mf+1], tsum);
                    }
                }
            }
            Ssum += (double)tsum;
        }

        // per-row reduction of (m,d): 16 partials per row
        __syncthreads();
#pragma unroll
        for (int mf = 0; mf < 4; mf++) {
#pragma unroll
            for (int h = 0; h < 2; h++) {
                int rloc = wm * 64 + mf * 16 + g + 8 * h;
                red_m[rloc][wn * 4 + t] = m[2 * mf + h];
                red_d[rloc][wn * 4 + t] = d[2 * mf + h];
            }
        }
        __syncthreads();
        if (tid < 128) {
            float M = -FLT_MAX, D = 0.f;
#pragma unroll
            for (int s = 0; s < 16; s++) {
                float mm = red_m[tid][s];
                float dd = red_d[tid][s];
                if (mm > M) { D = D * __expf(M - mm) + dd; M = mm; }
                else        { D += dd * __expf(mm - M); }
            }
            int x = x0 + tid;
            if (x < T) {
                int idx = rowOff(l) * 16 + b * T + x;
                g_row_m[idx] = M;
                g_row_d[idx] = D;
            }
        }
    }

    // block-reduce Ssum, apply -S term with level weight
    double v = Ssum;
#pragma unroll
    for (int o = 16; o > 0; o >>= 1) v += __shfl_down_sync(0xffffffffu, v, o);
    if (lid == 0) wsum[wid] = v;
    __syncthreads();
    if (tid == 0) {
        double tot = 0.0;
#pragma unroll
        for (int q = 0; q < 8; q++) tot += wsum[q];
        double wgt = 1.0 / (192.0 * (double)T * (double)(T - 1));
        atomicAdd(&g_acc, -wgt * tot);
    }
}

// ---------------------------------------------------------------------------
// Temporal kernel B: per (level,b) — global max M (rows + diagonal), then
// sum_x (T-1-x) * (M + log(d_x * exp(m_x - M) + eps))
__global__ void __launch_bounds__(256)
k_tempB(const float* __restrict__ z1, const float* __restrict__ z2) {
    int b = blockIdx.x;
    int l = blockIdx.y;
    int T = TTOP >> l;
    const float* zb = lvl_base(l, b, z1, z2);
    int base = rowOff(l) * 16 + b * T;
    int tid = threadIdx.x;

    __shared__ float smax[256];
    __shared__ double sd[256];

    float mloc = -FLT_MAX;
    for (int x = tid; x < T; x += 256) {
        const float4* row = reinterpret_cast<const float4*>(zb + (size_t)x * CDIM);
        float nrm = 0.f;
#pragma unroll
        for (int c = 0; c < 16; c++) {
            float4 vv = row[c];
            nrm += vv.x * vv.x + vv.y * vv.y + vv.z * vv.z + vv.w * vv.w;
        }
        mloc = fmaxf(mloc, fmaxf(nrm * 10.0f, g_row_m[base + x]));
    }
    smax[tid] = mloc;
    __syncthreads();
    for (int s = 128; s > 0; s >>= 1) {
        if (tid < s) smax[tid] = fmaxf(smax[tid], smax[tid + s]);
        __syncthreads();
    }
    float M = smax[0];

    double sum = 0.0;
    for (int x = tid; x < T; x += 256) {
        float mrow = g_row_m[base + x];
        float drow = g_row_d[base + x];
        float dg = drow * expf(mrow - M);
        float valrow = M + logf(dg + 1e-5f);
        sum += (double)(T - 1 - x) * (double)valrow;
    }
    sd[tid] = sum;
    __syncthreads();
    for (int s = 128; s > 0; s >>= 1) {
        if (tid < s) sd[tid] += sd[tid + s];
        __syncthreads();
    }
    if (tid == 0) {
        double wgt = 1.0 / (192.0 * (double)T * (double)(T - 1));
        atomicAdd(&g_acc, wgt * sd[0]);
    }
}

__global__ void k_fin(float* out) { out[0] = (float)g_acc; }

// ---------------------------------------------------------------------------
extern "C" void kernel_launch(void* const* d_in, const int* in_sizes, int n_in,
                              void* d_out, int out_size) {
    const float* z1 = (const float*)d_in[0];
    const float* z2 = (const float*)d_in[1];
    float* out = (float*)d_out;

    cudaFuncSetAttribute(k_tempA, cudaFuncAttributeMaxDynamicSharedMemorySize,
                         TA_DYN_SMEM);

    k_init<<<1, 1>>>();

    {
        int n = 2 * 512 * 2016;
        k_poolA<<<(n + 255) / 256, 256>>>(z1, z2);
    }
    {
        int n = 2 * 512 * 31;
        k_poolB<<<(n + 255) / 256, 256>>>();
    }

    k_inst<<<512, 256>>>(z1, z2);

    // blocks: sum over levels 0..10 of 16 * npair(level) = 352
    k_tempA<<<352, 256, TA_DYN_SMEM>>>(z1, z2);
    k_tempB<<<dim3(16, 11), 256>>>(z1, z2);

    k_fin<<<1, 1>>>(out);
}

// round 6
// speedup vs baseline: 2.4785x; 2.4785x over previous
#include <cuda_runtime.h>
#include <cstdint>
#include <float.h>
#include <math.h>

// ---------------------------------------------------------------------------
// TS2Vec hierarchical loss, B=8, T=2048, C=64, ALPHA=0.5, TAU=0.1, EPS=1e-5
// Round 6: 1-pass tf32 mma.sync Gram, lean max/denom epilogue,
//          closed-form sum-of-sims in k_tempB.
// ---------------------------------------------------------------------------

#define TTOP 2048
#define CDIM 64
#define K2 14.426950408889634f     /* 10 / ln(2) */

__device__ double g_acc;
__device__ __align__(16) float g_pyr[2][8 * 2047 * 64];   // pooled levels 1..11
__device__ float g_row_m[4094 * 16];                       // per-row max (s-units)
__device__ float g_row_d[4094 * 16];                       // per-row denom

__device__ __forceinline__ int pyrOff(int l) { return 512 * (2048 - (4096 >> l)); }
__device__ __forceinline__ int rowOff(int l) { return 4096 - (4096 >> l); }
__device__ __forceinline__ const float* lvl_base(int l, int b,
                                                 const float* z1, const float* z2) {
    int bb = b & 7;
    const float* z = (b < 8) ? z1 : z2;
    const float* p = (b < 8) ? g_pyr[0] : g_pyr[1];
    if (l == 0) return z + (size_t)bb * TTOP * CDIM;
    return p + pyrOff(l) + (size_t)bb * (size_t)(TTOP >> l) * CDIM;
}

__device__ __forceinline__ float tf32r(float x) {
    uint32_t r;
    asm("cvt.rna.tf32.f32 %0, %1;" : "=r"(r) : "f"(x));
    return __uint_as_float(r);
}

__device__ __forceinline__ void mma_tf32(float c[4], uint32_t a0, uint32_t a1,
                                         uint32_t a2, uint32_t a3,
                                         uint32_t b0, uint32_t b1) {
    asm volatile(
        "mma.sync.aligned.m16n8k8.row.col.f32.tf32.tf32.f32 "
        "{%0,%1,%2,%3}, {%4,%5,%6,%7}, {%8,%9}, {%0,%1,%2,%3};"
        : "+f"(c[0]), "+f"(c[1]), "+f"(c[2]), "+f"(c[3])
        : "r"(a0), "r"(a1), "r"(a2), "r"(a3), "r"(b0), "r"(b1));
}

// ---------------------------------------------------------------------------
__global__ void k_init() { g_acc = 0.0; }

__global__ void k_poolA(const float* __restrict__ z1, const float* __restrict__ z2) {
    int idx = blockIdx.x * blockDim.x + threadIdx.x;
    const int NPER = 512 * 2016;
    if (idx >= 2 * NPER) return;
    int tensor = (idx >= NPER) ? 1 : 0;
    int off = idx - tensor * NPER;
    const float* in = tensor ? z2 : z1;
    int l = 1, T = 1024;
    while (off >= 512 * T) { off -= 512 * T; ++l; T >>= 1; }
    int c = off & 63;
    int t = (off >> 6) % T;
    int b = (off >> 6) / T;
    int w = TTOP / T;
    const float* src = in + ((size_t)b * TTOP + (size_t)t * w) * CDIM + c;
    float m = src[0];
    for (int k = 1; k < w; k++) m = fmaxf(m, src[(size_t)k * CDIM]);
    g_pyr[tensor][pyrOff(l) + ((size_t)b * T + t) * CDIM + c] = m;
}

__global__ void k_poolB() {
    int idx = blockIdx.x * blockDim.x + threadIdx.x;
    const int NPER = 512 * 31;
    if (idx >= 2 * NPER) return;
    int tensor = (idx >= NPER) ? 1 : 0;
    int off = idx - tensor * NPER;
    int l = 7, T = 16;
    while (off >= 512 * T) { off -= 512 * T; ++l; T >>= 1; }
    int c = off & 63;
    int t = (off >> 6) % T;
    int b = (off >> 6) / T;
    int w = 32 / T;
    const float* src = g_pyr[tensor] + pyrOff(6) + ((size_t)b * 32 + (size_t)t * w) * CDIM + c;
    float m = src[0];
    for (int k = 1; k < w; k++) m = fmaxf(m, src[(size_t)k * CDIM]);
    g_pyr[tensor][pyrOff(l) + ((size_t)b * T + t) * CDIM + c] = m;
}

// ---------------------------------------------------------------------------
// Instance loss: warp-per-slice. 512 blocks x 8 warps = 4096 >= 4095 slices.
__global__ void __launch_bounds__(256)
k_inst(const float* __restrict__ z1, const float* __restrict__ z2) {
    __shared__ float zs[8][16][68];
    __shared__ float sim[8][16][17];
    __shared__ double wres[8];
    int tid = threadIdx.x;
    int w = tid >> 5, lid = tid & 31;
    int slice = blockIdx.x * 8 + w;
    double myres = 0.0;

    if (slice < 4095) {
        int l = 0, T = TTOP, t = slice;
        while (t >= T) { t -= T; ++l; T >>= 1; }

#pragma unroll
        for (int q = 0; q < 8; q++) {
            int e = lid + q * 32;
            int r = e >> 4, c4 = e & 15;
            const float* rowp = lvl_base(l, r, z1, z2) + (size_t)t * CDIM;
            *reinterpret_cast<float4*>(&zs[w][r][4 * c4]) =
                *reinterpret_cast<const float4*>(rowp + 4 * c4);
        }
        __syncwarp();

        int i = lid >> 1;
        int jb = (lid & 1) << 3;
#pragma unroll
        for (int q = 0; q < 8; q++) {
            int j = jb + q;
            float acc = 0.f;
#pragma unroll
            for (int k4 = 0; k4 < 16; k4++) {
                float4 a = *reinterpret_cast<const float4*>(&zs[w][i][4 * k4]);
                float4 b = *reinterpret_cast<const float4*>(&zs[w][j][4 * k4]);
                acc += a.x * b.x + a.y * b.y + a.z * b.z + a.w * b.w;
            }
            sim[w][i][j] = acc;
        }
        __syncwarp();

        float v = 0.f;
        if (lid < 16) {
            float m = -FLT_MAX;
#pragma unroll
            for (int jj = 0; jj < 16; jj++)
                if (jj != lid) m = fmaxf(m, sim[w][lid][jj]);
            float s = 0.f;
#pragma unroll
            for (int jj = 0; jj < 16; jj++)
                if (jj != lid) s += expf(sim[w][lid][jj] - m);
            int pos = (lid < 8) ? lid + 8 : lid - 8;
            v = m + logf(s) - sim[w][lid][pos];
        }
#pragma unroll
        for (int o = 16; o > 0; o >>= 1) v += __shfl_down_sync(0xffffffffu, v, o);
        if (lid == 0) myres = (double)v / (384.0 * (double)T);
    }
    if (lid == 0) wres[w] = myres;
    __syncthreads();
    if (tid == 0) {
        double tot = 0.0;
#pragma unroll
        for (int q = 0; q < 8; q++) tot += wres[q];
        atomicAdd(&g_acc, tot);
    }
}

// ---------------------------------------------------------------------------
// Temporal kernel A: 128x128 tiles, 1-pass tf32 mma.sync, row max + denom only.
// A(x) tile layout: float4 {A[r][c], A[r+8][c], A[r][c+4], A[r+8][c+4]},
//   addr = rp*36 + s*4 + t  (rp = (r>>4)*8 + (r&7), c = 8s+t), stride 36 f4.
// B(y) tile layout: float2 {B[n][c], B[n][c+4]}, addr = n*36 + s*4 + t.
#define TS 128
#define XA_F4 (64 * 36)                 /* 2304 float4 = 36864 B */
#define YB_F2 (128 * 36)                /* 4608 float2 = 36864 B */
#define TA_DYN_SMEM (XA_F4 * 16 + YB_F2 * 8)

__device__ __forceinline__ void load_xtileA(float4* xa, const float* zb,
                                            int r0, int T, int tid) {
#pragma unroll
    for (int it = 0; it < 2; it++) {
        int e = tid + it * 256;                 // 0..511 = (rp, s)
        int rp = e >> 3, s = e & 7;
        int group = rp >> 3, rr = rp & 7;
        int ra = r0 + group * 16 + rr;
        int rb = ra + 8;
        float4 u0 = make_float4(0.f, 0.f, 0.f, 0.f), u1 = u0, v0 = u0, v1 = u0;
        if (ra < T) {
            const float* p = zb + (size_t)ra * CDIM + 8 * s;
            u0 = *reinterpret_cast<const float4*>(p);
            u1 = *reinterpret_cast<const float4*>(p + 4);
        }
        if (rb < T) {
            const float* p = zb + (size_t)rb * CDIM + 8 * s;
            v0 = *reinterpret_cast<const float4*>(p);
            v1 = *reinterpret_cast<const float4*>(p + 4);
        }
        float4* dst = xa + rp * 36 + s * 4;
        dst[0] = make_float4(tf32r(u0.x), tf32r(v0.x), tf32r(u1.x), tf32r(v1.x));
        dst[1] = make_float4(tf32r(u0.y), tf32r(v0.y), tf32r(u1.y), tf32r(v1.y));
        dst[2] = make_float4(tf32r(u0.z), tf32r(v0.z), tf32r(u1.z), tf32r(v1.z));
        dst[3] = make_float4(tf32r(u0.w), tf32r(v0.w), tf32r(u1.w), tf32r(v1.w));
    }
}

__device__ __forceinline__ void load_ytileB(float2* yb, const float* zb,
                                            int r0, int T, int tid) {
#pragma unroll
    for (int it = 0; it < 4; it++) {
        int e = tid + it * 256;                 // 0..1023 = (n, s)
        int n = e >> 3, s = e & 7;
        float4 a = make_float4(0.f, 0.f, 0.f, 0.f), b = a;
        if (r0 + n < T) {
            const float* p = zb + (size_t)(r0 + n) * CDIM + 8 * s;
            a = *reinterpret_cast<const float4*>(p);
            b = *reinterpret_cast<const float4*>(p + 4);
        }
        float2* dst = yb + n * 36 + s * 4;
        *reinterpret_cast<float4*>(dst) =
            make_float4(tf32r(a.x), tf32r(b.x), tf32r(a.y), tf32r(b.y));
        *reinterpret_cast<float4*>(dst + 2) =
            make_float4(tf32r(a.z), tf32r(b.z), tf32r(a.w), tf32r(b.w));
    }
}

__global__ void __launch_bounds__(256, 1)
k_tempA(const float* __restrict__ z1, const float* __restrict__ z2) {
    extern __shared__ float4 dsm4[];
    float4* xa = dsm4;
    float2* yb = reinterpret_cast<float2*>(dsm4 + XA_F4);
    __shared__ float red_m[128][16];
    __shared__ float red_d[128][16];

    int tid = threadIdx.x;
    int wid = tid >> 5, lid = tid & 31;
    int wm = wid >> 2, wn = wid & 3;                // 2 x 4 warp grid
    int gq = lid >> 2, t = lid & 3;

    // decode block -> (level, b, xtile pair)
    int bid = blockIdx.x;
    int l = 0, T = TTOP, npair;
    for (;;) {
        int nt = (T + TS - 1) / TS; if (nt < 1) nt = 1;
        npair = (nt + 1) >> 1;
        int cnt = 16 * npair;
        if (bid < cnt) break;
        bid -= cnt; ++l; T >>= 1;
        if (l > 10) return;
    }
    int NT = (T + TS - 1) / TS; if (NT < 1) NT = 1;
    int b = bid / npair;
    int p = bid % npair;
    const float* zb = lvl_base(l, b, z1, z2);

    int xtiles[2];
    int nxt = 1;
    xtiles[0] = p;
    if (NT - 1 - p != p) { xtiles[1] = NT - 1 - p; nxt = 2; }

    for (int xi = 0; xi < nxt; xi++) {
        int xt = xtiles[xi];
        int x0 = xt * TS;
        __syncthreads();                            // smem reuse guard
        load_xtileA(xa, zb, x0, T, tid);

        float m[8], d[8];
#pragma unroll
        for (int q = 0; q < 8; q++) { m[q] = -FLT_MAX; d[q] = 0.f; }

        for (int yt = xt; yt < NT; yt++) {
            int y0 = yt * TS;
            __syncthreads();                        // prev reads done
            load_ytileB(yb, zb, y0, T, tid);
            __syncthreads();                        // tiles ready

            float acc[4][4][4];
#pragma unroll
            for (int mf = 0; mf < 4; mf++)
#pragma unroll
                for (int nf = 0; nf < 4; nf++)
#pragma unroll
                    for (int q = 0; q < 4; q++) acc[mf][nf][q] = 0.f;

#pragma unroll
            for (int s = 0; s < 8; s++) {
                float4 af[4];
#pragma unroll
                for (int mf = 0; mf < 4; mf++)
                    af[mf] = xa[((wm * 4 + mf) * 8 + gq) * 36 + s * 4 + t];
                uint32_t bbf[4][2];
#pragma unroll
                for (int nf = 0; nf < 4; nf++) {
                    float2 f = yb[(wn * 32 + nf * 8 + gq) * 36 + s * 4 + t];
                    bbf[nf][0] = __float_as_uint(f.x);
                    bbf[nf][1] = __float_as_uint(f.y);
                }
#pragma unroll
                for (int mf = 0; mf < 4; mf++)
#pragma unroll
                    for (int nf = 0; nf < 4; nf++)
                        mma_tf32(acc[mf][nf],
                                 __float_as_uint(af[mf].x), __float_as_uint(af[mf].y),
                                 __float_as_uint(af[mf].z), __float_as_uint(af[mf].w),
                                 bbf[nf][0], bbf[nf][1]);
            }

            bool fast = (yt > xt) && (x0 + TS <= T) && (y0 + TS <= T);
#pragma unroll
            for (int mf = 0; mf < 4; mf++) {
#pragma unroll
                for (int h = 0; h < 2; h++) {
                    int slot = 2 * mf + h;
                    float v[8];
#pragma unroll
                    for (int nf = 0; nf < 4; nf++) {
                        v[2 * nf]     = acc[mf][nf][2 * h];
                        v[2 * nf + 1] = acc[mf][nf][2 * h + 1];
                    }
                    if (!fast) {
                        int xr = x0 + wm * 64 + mf * 16 + gq + 8 * h;
#pragma unroll
                        for (int nf = 0; nf < 4; nf++) {
                            int yc = y0 + wn * 32 + nf * 8 + 2 * t;
                            if (!(yc > xr && yc < T && xr < T))
                                v[2 * nf] = -FLT_MAX;
                            if (!(yc + 1 > xr && yc + 1 < T && xr < T))
                                v[2 * nf + 1] = -FLT_MAX;
                        }
                    }
                    float g1 = fmaxf(fmaxf(v[0], v[1]), fmaxf(v[2], v[3]));
                    float g2 = fmaxf(fmaxf(v[4], v[5]), fmaxf(v[6], v[7]));
                    float gmax = fmaxf(g1, g2);
                    float nm = fmaxf(m[slot], gmax);
                    d[slot] *= exp2f(K2 * (m[slot] - nm));
                    m[slot] = nm;
                    float thr = nm - 2.0f;
                    float e = 0.f;
#pragma unroll
                    for (int j = 0; j < 8; j++)
                        if (v[j] > thr) e += exp2f(K2 * (v[j] - nm));
                    d[slot] += e;
                }
            }
        }

        // per-row reduction of (m,d): 16 partials per row
        __syncthreads();
#pragma unroll
        for (int mf = 0; mf < 4; mf++) {
#pragma unroll
            for (int h = 0; h < 2; h++) {
                int rloc = wm * 64 + mf * 16 + gq + 8 * h;
                red_m[rloc][wn * 4 + t] = m[2 * mf + h];
                red_d[rloc][wn * 4 + t] = d[2 * mf + h];
            }
        }
        __syncthreads();
        if (tid < 128) {
            float M = -FLT_MAX, D = 0.f;
#pragma unroll
            for (int s = 0; s < 16; s++) {
                float mm = red_m[tid][s];
                float dd = red_d[tid][s];
                if (mm > M) { D = D * exp2f(K2 * (M - mm)) + dd; M = mm; }
                else        { D += dd * exp2f(K2 * (mm - M)); }
            }
            int x = x0 + tid;
            if (x < T) {
                int idx = rowOff(l) * 16 + b * T + x;
                g_row_m[idx] = fmaxf(10.0f * M, -1e30f);
                g_row_d[idx] = D;
            }
        }
    }
}

// ---------------------------------------------------------------------------
// Temporal kernel B: per (level,b) — global max M (rows + diagonal),
// sum_x (T-1-x)*(M + log(d_x e^{m_x-M} + eps)), minus closed-form sum of sims:
//   sum_{y>x} scaled = 10*(|sum_x z_x|^2 - sum_x |z_x|^2)/2.
__global__ void __launch_bounds__(256)
k_tempB(const float* __restrict__ z1, const float* __restrict__ z2) {
    int b = blockIdx.x;
    int l = blockIdx.y;
    int T = TTOP >> l;
    const float* zb = lvl_base(l, b, z1, z2);
    int base = rowOff(l) * 16 + b * T;
    int tid = threadIdx.x;

    __shared__ float smax[256];
    __shared__ double sd[256];
    __shared__ float svec[4][64];

    // pass 1: per-row norms -> global max candidate + sum of norms
    float mloc = -FLT_MAX;
    float nrmp = 0.f;
    for (int x = tid; x < T; x += 256) {
        const float4* row = reinterpret_cast<const float4*>(zb + (size_t)x * CDIM);
        float nrm = 0.f;
#pragma unroll
        for (int c = 0; c < 16; c++) {
            float4 vv = row[c];
            nrm += vv.x * vv.x + vv.y * vv.y + vv.z * vv.z + vv.w * vv.w;
        }
        mloc = fmaxf(mloc, fmaxf(nrm * 10.0f, g_row_m[base + x]));
        nrmp += nrm;
    }
    smax[tid] = mloc;
    sd[tid] = (double)nrmp;

    // column sums for |sum z|^2
    {
        int c = tid & 63, rg = tid >> 6;
        float vs = 0.f;
        for (int x = rg; x < T; x += 4) vs += zb[(size_t)x * CDIM + c];
        svec[rg][c] = vs;
    }
    __syncthreads();
    for (int s = 128; s > 0; s >>= 1) {
        if (tid < s) {
            smax[tid] = fmaxf(smax[tid], smax[tid + s]);
            sd[tid] += sd[tid + s];
        }
        __syncthreads();
    }
    float M = smax[0];
    double nrmtot = sd[0];
    __syncthreads();

    double s2 = 0.0;
    if (tid < 64) {
        float S = svec[0][tid] + svec[1][tid] + svec[2][tid] + svec[3][tid];
        s2 = (double)S * (double)S;
    }
    sd[tid] = s2;
    __syncthreads();
    for (int s = 128; s > 0; s >>= 1) {
        if (tid < s) sd[tid] += sd[tid + s];
        __syncthreads();
    }
    double S2 = sd[0];
    __syncthreads();

    double sum = 0.0;
    for (int x = tid; x < T; x += 256) {
        float mrow = g_row_m[base + x];
        float drow = g_row_d[base + x];
        float dg = drow * expf(mrow - M);
        float valrow = M + logf(dg + 1e-5f);
        sum += (double)(T - 1 - x) * (double)valrow;
    }
    sd[tid] = sum;
    __syncthreads();
    for (int s = 128; s > 0; s >>= 1) {
        if (tid < s) sd[tid] += sd[tid + s];
        __syncthreads();
    }
    if (tid == 0) {
        double Ssum = 5.0 * (S2 - nrmtot);     // sum of scaled sims over y>x
        double wgt = 1.0 / (192.0 * (double)T * (double)(T - 1));
        atomicAdd(&g_acc, wgt * (sd[0] - Ssum));
    }
}

__global__ void k_fin(float* out) { out[0] = (float)g_acc; }

// ---------------------------------------------------------------------------
extern "C" void kernel_launch(void* const* d_in, const int* in_sizes, int n_in,
                              void* d_out, int out_size) {
    const float* z1 = (const float*)d_in[0];
    const float* z2 = (const float*)d_in[1];
    float* out = (float*)d_out;

    cudaFuncSetAttribute(k_tempA, cudaFuncAttributeMaxDynamicSharedMemorySize,
                         TA_DYN_SMEM);

    k_init<<<1, 1>>>();

    {
        int n = 2 * 512 * 2016;
        k_poolA<<<(n + 255) / 256, 256>>>(z1, z2);
    }
    {
        int n = 2 * 512 * 31;
        k_poolB<<<(n + 255) / 256, 256>>>();
    }

    k_inst<<<512, 256>>>(z1, z2);

    // blocks: sum over levels 0..10 of 16 * npair(level) = 352
    k_tempA<<<352, 256, TA_DYN_SMEM>>>(z1, z2);
    k_tempB<<<dim3(16, 11), 256>>>(z1, z2);

    k_fin<<<1, 1>>>(out);
}

// round 7
// speedup vs baseline: 2.6863x; 1.0839x over previous
#include <cuda_runtime.h>
#include <cstdint>
#include <float.h>
#include <math.h>

// ---------------------------------------------------------------------------
// TS2Vec hierarchical loss, B=8, T=2048, C=64, ALPHA=0.5, TAU=0.1, EPS=1e-5
// Round 7: tempA occupancy-2 (reg cap); k_inst on tf32 mma.sync.
// ---------------------------------------------------------------------------

#define TTOP 2048
#define CDIM 64
#define K2 14.426950408889634f     /* 10 / ln(2) */

__device__ double g_acc;
__device__ __align__(16) float g_pyr[2][8 * 2047 * 64];   // pooled levels 1..11
__device__ float g_row_m[4094 * 16];                       // per-row max (s-units)
__device__ float g_row_d[4094 * 16];                       // per-row denom

__device__ __forceinline__ int pyrOff(int l) { return 512 * (2048 - (4096 >> l)); }
__device__ __forceinline__ int rowOff(int l) { return 4096 - (4096 >> l); }
__device__ __forceinline__ const float* lvl_base(int l, int b,
                                                 const float* z1, const float* z2) {
    int bb = b & 7;
    const float* z = (b < 8) ? z1 : z2;
    const float* p = (b < 8) ? g_pyr[0] : g_pyr[1];
    if (l == 0) return z + (size_t)bb * TTOP * CDIM;
    return p + pyrOff(l) + (size_t)bb * (size_t)(TTOP >> l) * CDIM;
}

__device__ __forceinline__ float tf32r(float x) {
    uint32_t r;
    asm("cvt.rna.tf32.f32 %0, %1;" : "=r"(r) : "f"(x));
    return __uint_as_float(r);
}
__device__ __forceinline__ float4 tf32r4(float4 v) {
    return make_float4(tf32r(v.x), tf32r(v.y), tf32r(v.z), tf32r(v.w));
}

__device__ __forceinline__ void mma_tf32(float c[4], uint32_t a0, uint32_t a1,
                                         uint32_t a2, uint32_t a3,
                                         uint32_t b0, uint32_t b1) {
    asm volatile(
        "mma.sync.aligned.m16n8k8.row.col.f32.tf32.tf32.f32 "
        "{%0,%1,%2,%3}, {%4,%5,%6,%7}, {%8,%9}, {%0,%1,%2,%3};"
        : "+f"(c[0]), "+f"(c[1]), "+f"(c[2]), "+f"(c[3])
        : "r"(a0), "r"(a1), "r"(a2), "r"(a3), "r"(b0), "r"(b1));
}

// ---------------------------------------------------------------------------
__global__ void k_init() { g_acc = 0.0; }

__global__ void k_poolA(const float* __restrict__ z1, const float* __restrict__ z2) {
    int idx = blockIdx.x * blockDim.x + threadIdx.x;
    const int NPER = 512 * 2016;
    if (idx >= 2 * NPER) return;
    int tensor = (idx >= NPER) ? 1 : 0;
    int off = idx - tensor * NPER;
    const float* in = tensor ? z2 : z1;
    int l = 1, T = 1024;
    while (off >= 512 * T) { off -= 512 * T; ++l; T >>= 1; }
    int c = off & 63;
    int t = (off >> 6) % T;
    int b = (off >> 6) / T;
    int w = TTOP / T;
    const float* src = in + ((size_t)b * TTOP + (size_t)t * w) * CDIM + c;
    float m = src[0];
    for (int k = 1; k < w; k++) m = fmaxf(m, src[(size_t)k * CDIM]);
    g_pyr[tensor][pyrOff(l) + ((size_t)b * T + t) * CDIM + c] = m;
}

__global__ void k_poolB() {
    int idx = blockIdx.x * blockDim.x + threadIdx.x;
    const int NPER = 512 * 31;
    if (idx >= 2 * NPER) return;
    int tensor = (idx >= NPER) ? 1 : 0;
    int off = idx - tensor * NPER;
    int l = 7, T = 16;
    while (off >= 512 * T) { off -= 512 * T; ++l; T >>= 1; }
    int c = off & 63;
    int t = (off >> 6) % T;
    int b = (off >> 6) / T;
    int w = 32 / T;
    const float* src = g_pyr[tensor] + pyrOff(6) + ((size_t)b * 32 + (size_t)t * w) * CDIM + c;
    float m = src[0];
    for (int k = 1; k < w; k++) m = fmaxf(m, src[(size_t)k * CDIM]);
    g_pyr[tensor][pyrOff(l) + ((size_t)b * T + t) * CDIM + c] = m;
}

// ---------------------------------------------------------------------------
// Instance loss via tf32 mma: one warp per slice, 4 warps/block.
// A pack: float4 {A[r][c], A[r+8][c], A[r][c+4], A[r+8][c+4]} at [r][s*4+t].
// B pack: float2 {A[n][c], A[n][c+4]} at [n][s*4+t].   (c = 8s+t)
__global__ void __launch_bounds__(128)
k_inst(const float* __restrict__ z1, const float* __restrict__ z2) {
    __shared__ float4 apack[4][8 * 36];
    __shared__ float2 bpack[4][16 * 36];
    __shared__ double wres[4];
    int tid = threadIdx.x;
    int w = tid >> 5, lid = tid & 31;
    int gq = lid >> 2, t4 = lid & 3;
    int slice = blockIdx.x * 4 + w;
    double myres = 0.0;

    if (slice < 4095) {
        int l = 0, T = TTOP, tt = slice;
        while (tt >= T) { tt -= T; ++l; T >>= 1; }

        // Build packs: 2 tasks/lane, task=(rp,s); rows rp & rp+8, cols 8s..8s+7.
#pragma unroll
        for (int i = 0; i < 2; i++) {
            int task = lid + 32 * i;
            int rp = task >> 3, s = task & 7;
            const float* pa = lvl_base(l, rp, z1, z2) + (size_t)tt * CDIM + 8 * s;
            const float* pb = lvl_base(l, rp + 8, z1, z2) + (size_t)tt * CDIM + 8 * s;
            float4 u0 = tf32r4(*reinterpret_cast<const float4*>(pa));
            float4 u1 = tf32r4(*reinterpret_cast<const float4*>(pa + 4));
            float4 v0 = tf32r4(*reinterpret_cast<const float4*>(pb));
            float4 v1 = tf32r4(*reinterpret_cast<const float4*>(pb + 4));
            float4* ap = &apack[w][rp * 36 + s * 4];
            ap[0] = make_float4(u0.x, v0.x, u1.x, v1.x);
            ap[1] = make_float4(u0.y, v0.y, u1.y, v1.y);
            ap[2] = make_float4(u0.z, v0.z, u1.z, v1.z);
            ap[3] = make_float4(u0.w, v0.w, u1.w, v1.w);
            float2* bp0 = &bpack[w][rp * 36 + s * 4];
            bp0[0] = make_float2(u0.x, u1.x);
            bp0[1] = make_float2(u0.y, u1.y);
            bp0[2] = make_float2(u0.z, u1.z);
            bp0[3] = make_float2(u0.w, u1.w);
            float2* bp1 = &bpack[w][(rp + 8) * 36 + s * 4];
            bp1[0] = make_float2(v0.x, v1.x);
            bp1[1] = make_float2(v0.y, v1.y);
            bp1[2] = make_float2(v0.z, v1.z);
            bp1[3] = make_float2(v0.w, v1.w);
        }
        __syncwarp();

        float acc0[4] = {0.f, 0.f, 0.f, 0.f};
        float acc1[4] = {0.f, 0.f, 0.f, 0.f};
#pragma unroll
        for (int s = 0; s < 8; s++) {
            float4 a = apack[w][gq * 36 + s * 4 + t4];
            float2 b0 = bpack[w][gq * 36 + s * 4 + t4];
            float2 b1 = bpack[w][(8 + gq) * 36 + s * 4 + t4];
            mma_tf32(acc0, __float_as_uint(a.x), __float_as_uint(a.y),
                     __float_as_uint(a.z), __float_as_uint(a.w),
                     __float_as_uint(b0.x), __float_as_uint(b0.y));
            mma_tf32(acc1, __float_as_uint(a.x), __float_as_uint(a.y),
                     __float_as_uint(a.z), __float_as_uint(a.w),
                     __float_as_uint(b1.x), __float_as_uint(b1.y));
        }

        // Lane holds sim rows {gq, gq+8} x cols {2t,2t+1, 8+2t, 9+2t}.
        int j0 = 2 * t4, j1 = 2 * t4 + 1;
        // row A = gq (diag at j<8, pos = gq+8)
        float vA0 = (j0 == gq) ? -FLT_MAX : acc0[0];
        float vA1 = (j1 == gq) ? -FLT_MAX : acc0[1];
        float vA2 = acc1[0], vA3 = acc1[1];
        // row B = gq+8 (diag at j>=8, pos = gq)
        float vB0 = acc0[2], vB1 = acc0[3];
        float vB2 = (j0 == gq) ? -FLT_MAX : acc1[2];
        float vB3 = (j1 == gq) ? -FLT_MAX : acc1[3];

        float mA = fmaxf(fmaxf(vA0, vA1), fmaxf(vA2, vA3));
        float mB = fmaxf(fmaxf(vB0, vB1), fmaxf(vB2, vB3));
        mA = fmaxf(mA, __shfl_xor_sync(0xffffffffu, mA, 1));
        mA = fmaxf(mA, __shfl_xor_sync(0xffffffffu, mA, 2));
        mB = fmaxf(mB, __shfl_xor_sync(0xffffffffu, mB, 1));
        mB = fmaxf(mB, __shfl_xor_sync(0xffffffffu, mB, 2));

        float eA = __expf(vA0 - mA) + __expf(vA1 - mA) +
                   __expf(vA2 - mA) + __expf(vA3 - mA);
        float eB = __expf(vB0 - mB) + __expf(vB1 - mB) +
                   __expf(vB2 - mB) + __expf(vB3 - mB);
        eA += __shfl_xor_sync(0xffffffffu, eA, 1);
        eA += __shfl_xor_sync(0xffffffffu, eA, 2);
        eB += __shfl_xor_sync(0xffffffffu, eB, 1);
        eB += __shfl_xor_sync(0xffffffffu, eB, 2);

        // positives: sim[gq][gq+8] (col 8+2t or 9+2t) and sim[gq+8][gq]
        float pA = ((j0 == gq) ? acc1[0] : 0.f) + ((j1 == gq) ? acc1[1] : 0.f);
        float pB = ((j0 == gq) ? acc0[2] : 0.f) + ((j1 == gq) ? acc0[3] : 0.f);
        pA += __shfl_xor_sync(0xffffffffu, pA, 1);
        pA += __shfl_xor_sync(0xffffffffu, pA, 2);
        pB += __shfl_xor_sync(0xffffffffu, pB, 1);
        pB += __shfl_xor_sync(0xffffffffu, pB, 2);

        float v = (mA + __logf(eA) - pA) + (mB + __logf(eB) - pB);
        v = (t4 == 0) ? v : 0.f;
#pragma unroll
        for (int o = 16; o > 0; o >>= 1)
            v += __shfl_down_sync(0xffffffffu, v, o);
        if (lid == 0) myres = (double)v / (384.0 * (double)T);
    }
    if (lid == 0) wres[w] = myres;
    __syncthreads();
    if (tid == 0) {
        double tot = 0.0;
#pragma unroll
        for (int q = 0; q < 4; q++) tot += wres[q];
        atomicAdd(&g_acc, tot);
    }
}

// ---------------------------------------------------------------------------
// Temporal kernel A: 128x128 tiles, 1-pass tf32 mma.sync, row max + denom only.
#define TS 128
#define XA_F4 (64 * 36)                 /* 2304 float4 = 36864 B */
#define YB_F2 (128 * 36)                /* 4608 float2 = 36864 B */
#define TA_DYN_SMEM (XA_F4 * 16 + YB_F2 * 8)

__device__ __forceinline__ void load_xtileA(float4* xa, const float* zb,
                                            int r0, int T, int tid) {
#pragma unroll
    for (int it = 0; it < 2; it++) {
        int e = tid + it * 256;                 // 0..511 = (rp, s)
        int rp = e >> 3, s = e & 7;
        int group = rp >> 3, rr = rp & 7;
        int ra = r0 + group * 16 + rr;
        int rb = ra + 8;
        float4 u0 = make_float4(0.f, 0.f, 0.f, 0.f), u1 = u0, v0 = u0, v1 = u0;
        if (ra < T) {
            const float* p = zb + (size_t)ra * CDIM + 8 * s;
            u0 = *reinterpret_cast<const float4*>(p);
            u1 = *reinterpret_cast<const float4*>(p + 4);
        }
        if (rb < T) {
            const float* p = zb + (size_t)rb * CDIM + 8 * s;
            v0 = *reinterpret_cast<const float4*>(p);
            v1 = *reinterpret_cast<const float4*>(p + 4);
        }
        float4* dst = xa + rp * 36 + s * 4;
        dst[0] = make_float4(tf32r(u0.x), tf32r(v0.x), tf32r(u1.x), tf32r(v1.x));
        dst[1] = make_float4(tf32r(u0.y), tf32r(v0.y), tf32r(u1.y), tf32r(v1.y));
        dst[2] = make_float4(tf32r(u0.z), tf32r(v0.z), tf32r(u1.z), tf32r(v1.z));
        dst[3] = make_float4(tf32r(u0.w), tf32r(v0.w), tf32r(u1.w), tf32r(v1.w));
    }
}

__device__ __forceinline__ void load_ytileB(float2* yb, const float* zb,
                                            int r0, int T, int tid) {
#pragma unroll
    for (int it = 0; it < 4; it++) {
        int e = tid + it * 256;                 // 0..1023 = (n, s)
        int n = e >> 3, s = e & 7;
        float4 a = make_float4(0.f, 0.f, 0.f, 0.f), b = a;
        if (r0 + n < T) {
            const float* p = zb + (size_t)(r0 + n) * CDIM + 8 * s;
            a = *reinterpret_cast<const float4*>(p);
            b = *reinterpret_cast<const float4*>(p + 4);
        }
        float2* dst = yb + n * 36 + s * 4;
        *reinterpret_cast<float4*>(dst) =
            make_float4(tf32r(a.x), tf32r(b.x), tf32r(a.y), tf32r(b.y));
        *reinterpret_cast<float4*>(dst + 2) =
            make_float4(tf32r(a.z), tf32r(b.z), tf32r(a.w), tf32r(b.w));
    }
}

__global__ void __launch_bounds__(256, 2)
k_tempA(const float* __restrict__ z1, const float* __restrict__ z2) {
    extern __shared__ float4 dsm4[];
    float4* xa = dsm4;
    float2* yb = reinterpret_cast<float2*>(dsm4 + XA_F4);
    __shared__ float red_m[128][16];
    __shared__ float red_d[128][16];

    int tid = threadIdx.x;
    int wid = tid >> 5, lid = tid & 31;
    int wm = wid >> 2, wn = wid & 3;                // 2 x 4 warp grid
    int gq = lid >> 2, t = lid & 3;

    // decode block -> (level, b, xtile pair)
    int bid = blockIdx.x;
    int l = 0, T = TTOP, npair;
    for (;;) {
        int nt = (T + TS - 1) / TS; if (nt < 1) nt = 1;
        npair = (nt + 1) >> 1;
        int cnt = 16 * npair;
        if (bid < cnt) break;
        bid -= cnt; ++l; T >>= 1;
        if (l > 10) return;
    }
    int NT = (T + TS - 1) / TS; if (NT < 1) NT = 1;
    int b = bid / npair;
    int p = bid % npair;
    const float* zb = lvl_base(l, b, z1, z2);

    int xtiles[2];
    int nxt = 1;
    xtiles[0] = p;
    if (NT - 1 - p != p) { xtiles[1] = NT - 1 - p; nxt = 2; }

    for (int xi = 0; xi < nxt; xi++) {
        int xt = xtiles[xi];
        int x0 = xt * TS;
        __syncthreads();                            // smem reuse guard
        load_xtileA(xa, zb, x0, T, tid);

        float m[8], d[8];
#pragma unroll
        for (int q = 0; q < 8; q++) { m[q] = -FLT_MAX; d[q] = 0.f; }

        for (int yt = xt; yt < NT; yt++) {
            int y0 = yt * TS;
            __syncthreads();                        // prev reads done
            load_ytileB(yb, zb, y0, T, tid);
            __syncthreads();                        // tiles ready

            float acc[4][4][4];
#pragma unroll
            for (int mf = 0; mf < 4; mf++)
#pragma unroll
                for (int nf = 0; nf < 4; nf++)
#pragma unroll
                    for (int q = 0; q < 4; q++) acc[mf][nf][q] = 0.f;

#pragma unroll
            for (int s = 0; s < 8; s++) {
                float4 af[4];
#pragma unroll
                for (int mf = 0; mf < 4; mf++)
                    af[mf] = xa[((wm * 4 + mf) * 8 + gq) * 36 + s * 4 + t];
                uint32_t bbf[4][2];
#pragma unroll
                for (int nf = 0; nf < 4; nf++) {
                    float2 f = yb[(wn * 32 + nf * 8 + gq) * 36 + s * 4 + t];
                    bbf[nf][0] = __float_as_uint(f.x);
                    bbf[nf][1] = __float_as_uint(f.y);
                }
#pragma unroll
                for (int mf = 0; mf < 4; mf++)
#pragma unroll
                    for (int nf = 0; nf < 4; nf++)
                        mma_tf32(acc[mf][nf],
                                 __float_as_uint(af[mf].x), __float_as_uint(af[mf].y),
                                 __float_as_uint(af[mf].z), __float_as_uint(af[mf].w),
                                 bbf[nf][0], bbf[nf][1]);
            }

            bool fast = (yt > xt) && (x0 + TS <= T) && (y0 + TS <= T);
#pragma unroll
            for (int mf = 0; mf < 4; mf++) {
#pragma unroll
                for (int h = 0; h < 2; h++) {
                    int slot = 2 * mf + h;
                    float v[8];
#pragma unroll
                    for (int nf = 0; nf < 4; nf++) {
                        v[2 * nf]     = acc[mf][nf][2 * h];
                        v[2 * nf + 1] = acc[mf][nf][2 * h + 1];
                    }
                    if (!fast) {
                        int xr = x0 + wm * 64 + mf * 16 + gq + 8 * h;
#pragma unroll
                        for (int nf = 0; nf < 4; nf++) {
                            int yc = y0 + wn * 32 + nf * 8 + 2 * t;
                            if (!(yc > xr && yc < T && xr < T))
                                v[2 * nf] = -FLT_MAX;
                            if (!(yc + 1 > xr && yc + 1 < T && xr < T))
                                v[2 * nf + 1] = -FLT_MAX;
                        }
                    }
                    float g1 = fmaxf(fmaxf(v[0], v[1]), fmaxf(v[2], v[3]));
                    float g2 = fmaxf(fmaxf(v[4], v[5]), fmaxf(v[6], v[7]));
                    float gmax = fmaxf(g1, g2);
                    float nm = fmaxf(m[slot], gmax);
                    d[slot] *= exp2f(K2 * (m[slot] - nm));
                    m[slot] = nm;
                    float thr = nm - 2.0f;
                    float e = 0.f;
#pragma unroll
                    for (int j = 0; j < 8; j++)
                        if (v[j] > thr) e += exp2f(K2 * (v[j] - nm));
                    d[slot] += e;
                }
            }
        }

        // per-row reduction of (m,d): 16 partials per row
        __syncthreads();
#pragma unroll
        for (int mf = 0; mf < 4; mf++) {
#pragma unroll
            for (int h = 0; h < 2; h++) {
                int rloc = wm * 64 + mf * 16 + gq + 8 * h;
                red_m[rloc][wn * 4 + t] = m[2 * mf + h];
                red_d[rloc][wn * 4 + t] = d[2 * mf + h];
            }
        }
        __syncthreads();
        if (tid < 128) {
            float M = -FLT_MAX, D = 0.f;
#pragma unroll
            for (int s = 0; s < 16; s++) {
                float mm = red_m[tid][s];
                float dd = red_d[tid][s];
                if (mm > M) { D = D * exp2f(K2 * (M - mm)) + dd; M = mm; }
                else        { D += dd * exp2f(K2 * (mm - M)); }
            }
            int x = x0 + tid;
            if (x < T) {
                int idx = rowOff(l) * 16 + b * T + x;
                g_row_m[idx] = fmaxf(10.0f * M, -1e30f);
                g_row_d[idx] = D;
            }
        }
    }
}

// ---------------------------------------------------------------------------
// Temporal kernel B: per (level,b) — global max M (rows + diagonal),
// sum_x (T-1-x)*(M + log(d_x e^{m_x-M} + eps)), minus closed-form sum of sims.
__global__ void __launch_bounds__(256)
k_tempB(const float* __restrict__ z1, const float* __restrict__ z2) {
    int b = blockIdx.x;
    int l = blockIdx.y;
    int T = TTOP >> l;
    const float* zb = lvl_base(l, b, z1, z2);
    int base = rowOff(l) * 16 + b * T;
    int tid = threadIdx.x;

    __shared__ float smax[256];
    __shared__ double sd[256];
    __shared__ float svec[4][64];

    float mloc = -FLT_MAX;
    float nrmp = 0.f;
    for (int x = tid; x < T; x += 256) {
        const float4* row = reinterpret_cast<const float4*>(zb + (size_t)x * CDIM);
        float nrm = 0.f;
#pragma unroll
        for (int c = 0; c < 16; c++) {
            float4 vv = row[c];
            nrm += vv.x * vv.x + vv.y * vv.y + vv.z * vv.z + vv.w * vv.w;
        }
        mloc = fmaxf(mloc, fmaxf(nrm * 10.0f, g_row_m[base + x]));
        nrmp += nrm;
    }
    smax[tid] = mloc;
    sd[tid] = (double)nrmp;

    {
        int c = tid & 63, rg = tid >> 6;
        float vs = 0.f;
        for (int x = rg; x < T; x += 4) vs += zb[(size_t)x * CDIM + c];
        svec[rg][c] = vs;
    }
    __syncthreads();
    for (int s = 128; s > 0; s >>= 1) {
        if (tid < s) {
            smax[tid] = fmaxf(smax[tid], smax[tid + s]);
            sd[tid] += sd[tid + s];
        }
        __syncthreads();
    }
    float M = smax[0];
    double nrmtot = sd[0];
    __syncthreads();

    double s2 = 0.0;
    if (tid < 64) {
        float S = svec[0][tid] + svec[1][tid] + svec[2][tid] + svec[3][tid];
        s2 = (double)S * (double)S;
    }
    sd[tid] = s2;
    __syncthreads();
    for (int s = 128; s > 0; s >>= 1) {
        if (tid < s) sd[tid] += sd[tid + s];
        __syncthreads();
    }
    double S2 = sd[0];
    __syncthreads();

    double sum = 0.0;
    for (int x = tid; x < T; x += 256) {
        float mrow = g_row_m[base + x];
        float drow = g_row_d[base + x];
        float dg = drow * expf(mrow - M);
        float valrow = M + logf(dg + 1e-5f);
        sum += (double)(T - 1 - x) * (double)valrow;
    }
    sd[tid] = sum;
    __syncthreads();
    for (int s = 128; s > 0; s >>= 1) {
        if (tid < s) sd[tid] += sd[tid + s];
        __syncthreads();
    }
    if (tid == 0) {
        double Ssum = 5.0 * (S2 - nrmtot);
        double wgt = 1.0 / (192.0 * (double)T * (double)(T - 1));
        atomicAdd(&g_acc, wgt * (sd[0] - Ssum));
    }
}

__global__ void k_fin(float* out) { out[0] = (float)g_acc; }

// ---------------------------------------------------------------------------
extern "C" void kernel_launch(void* const* d_in, const int* in_sizes, int n_in,
                              void* d_out, int out_size) {
    const float* z1 = (const float*)d_in[0];
    const float* z2 = (const float*)d_in[1];
    float* out = (float*)d_out;

    cudaFuncSetAttribute(k_tempA, cudaFuncAttributeMaxDynamicSharedMemorySize,
                         TA_DYN_SMEM);

    k_init<<<1, 1>>>();

    {
        int n = 2 * 512 * 2016;
        k_poolA<<<(n + 255) / 256, 256>>>(z1, z2);
    }
    {
        int n = 2 * 512 * 31;
        k_poolB<<<(n + 255) / 256, 256>>>();
    }

    k_inst<<<1024, 128>>>(z1, z2);

    // blocks: sum over levels 0..10 of 16 * npair(level) = 352
    k_tempA<<<352, 256, TA_DYN_SMEM>>>(z1, z2);
    k_tempB<<<dim3(16, 11), 256>>>(z1, z2);

    k_fin<<<1, 1>>>(out);
}

// round 9
// speedup vs baseline: 2.8873x; 1.0748x over previous
#include <cuda_runtime.h>
#include <cstdint>
#include <float.h>
#include <math.h>

// ---------------------------------------------------------------------------
// TS2Vec hierarchical loss, B=8, T=2048, C=64, ALPHA=0.5, TAU=0.1, EPS=1e-5
// Round 9 (= round 8 resubmit after infra failure, + rhs>0 guard in k_rows):
// temporal Gram eliminated via Cauchy-Schwarz underflow proof.
//   M = 10*max|z|^2 always (C-S). Rows with 10|z_x||z|max < M-60 provably give
//   denom+EPS == EPS in the reference's own fp32 -> val = M + log(EPS) - s.
//   Only flagged rows (C-S bound close to M) get exact sparse SIMT fallback.
// ---------------------------------------------------------------------------

#define TTOP 2048
#define CDIM 64

__device__ double g_acc;
__device__ __align__(16) float g_pyr[2][8 * 2047 * 64];   // pooled levels 1..11
__device__ float g_row_m[4094 * 16];                       // per-row max (s-units)
__device__ float g_row_d[4094 * 16];                       // per-row denom
__device__ float g_norm[4094 * 16];                        // per-row |z|^2
__device__ float g_M[11 * 16];                             // per (l,b): 10*max|z|^2

__device__ __forceinline__ int pyrOff(int l) { return 512 * (2048 - (4096 >> l)); }
__device__ __forceinline__ int rowOff(int l) { return 4096 - (4096 >> l); }
__device__ __forceinline__ const float* lvl_base(int l, int b,
                                                 const float* z1, const float* z2) {
    int bb = b & 7;
    const float* z = (b < 8) ? z1 : z2;
    const float* p = (b < 8) ? g_pyr[0] : g_pyr[1];
    if (l == 0) return z + (size_t)bb * TTOP * CDIM;
    return p + pyrOff(l) + (size_t)bb * (size_t)(TTOP >> l) * CDIM;
}

__device__ __forceinline__ float tf32r(float x) {
    uint32_t r;
    asm("cvt.rna.tf32.f32 %0, %1;" : "=r"(r) : "f"(x));
    return __uint_as_float(r);
}
__device__ __forceinline__ float4 tf32r4(float4 v) {
    return make_float4(tf32r(v.x), tf32r(v.y), tf32r(v.z), tf32r(v.w));
}

__device__ __forceinline__ void mma_tf32(float c[4], uint32_t a0, uint32_t a1,
                                         uint32_t a2, uint32_t a3,
                                         uint32_t b0, uint32_t b1) {
    asm volatile(
        "mma.sync.aligned.m16n8k8.row.col.f32.tf32.tf32.f32 "
        "{%0,%1,%2,%3}, {%4,%5,%6,%7}, {%8,%9}, {%0,%1,%2,%3};"
        : "+f"(c[0]), "+f"(c[1]), "+f"(c[2]), "+f"(c[3])
        : "r"(a0), "r"(a1), "r"(a2), "r"(a3), "r"(b0), "r"(b1));
}

// ---------------------------------------------------------------------------
__global__ void k_poolA(const float* __restrict__ z1, const float* __restrict__ z2) {
    int idx = blockIdx.x * blockDim.x + threadIdx.x;
    const int NPER = 512 * 2016;
    if (idx >= 2 * NPER) return;
    int tensor = (idx >= NPER) ? 1 : 0;
    int off = idx - tensor * NPER;
    const float* in = tensor ? z2 : z1;
    int l = 1, T = 1024;
    while (off >= 512 * T) { off -= 512 * T; ++l; T >>= 1; }
    int c = off & 63;
    int t = (off >> 6) % T;
    int b = (off >> 6) / T;
    int w = TTOP / T;
    const float* src = in + ((size_t)b * TTOP + (size_t)t * w) * CDIM + c;
    float m = src[0];
    for (int k = 1; k < w; k++) m = fmaxf(m, src[(size_t)k * CDIM]);
    g_pyr[tensor][pyrOff(l) + ((size_t)b * T + t) * CDIM + c] = m;
}

__global__ void k_poolB() {
    int idx = blockIdx.x * blockDim.x + threadIdx.x;
    const int NPER = 512 * 31;
    if (idx >= 2 * NPER) return;
    int tensor = (idx >= NPER) ? 1 : 0;
    int off = idx - tensor * NPER;
    int l = 7, T = 16;
    while (off >= 512 * T) { off -= 512 * T; ++l; T >>= 1; }
    int c = off & 63;
    int t = (off >> 6) % T;
    int b = (off >> 6) / T;
    int w = 32 / T;
    const float* src = g_pyr[tensor] + pyrOff(6) + ((size_t)b * 32 + (size_t)t * w) * CDIM + c;
    float m = src[0];
    for (int k = 1; k < w; k++) m = fmaxf(m, src[(size_t)k * CDIM]);
    g_pyr[tensor][pyrOff(l) + ((size_t)b * T + t) * CDIM + c] = m;
}

// ---------------------------------------------------------------------------
// Row norms + per-(l,b) scaled max diag. Also zeroes g_acc.
__global__ void __launch_bounds__(256)
k_norm(const float* __restrict__ z1, const float* __restrict__ z2) {
    int b = blockIdx.x;          // 0..15
    int l = blockIdx.y;          // 0..10
    int T = TTOP >> l;
    const float* zb = lvl_base(l, b, z1, z2);
    int base = rowOff(l) * 16 + b * T;
    int tid = threadIdx.x;
    if (b == 0 && l == 0 && tid == 0) g_acc = 0.0;

    __shared__ float smax[256];
    float mx = 0.f;
    for (int x = tid; x < T; x += 256) {
        const float4* row = reinterpret_cast<const float4*>(zb + (size_t)x * CDIM);
        float nrm = 0.f;
#pragma unroll
        for (int c = 0; c < 16; c++) {
            float4 v = row[c];
            nrm += v.x * v.x + v.y * v.y + v.z * v.z + v.w * v.w;
        }
        g_norm[base + x] = nrm;
        mx = fmaxf(mx, nrm);
    }
    smax[tid] = mx;
    __syncthreads();
    for (int s = 128; s > 0; s >>= 1) {
        if (tid < s) smax[tid] = fmaxf(smax[tid], smax[tid + s]);
        __syncthreads();
    }
    if (tid == 0) g_M[l * 16 + b] = 10.f * smax[0];
}

// ---------------------------------------------------------------------------
// Per-row flag test + sparse exact fallback. One warp per row (65504 rows).
// Skip (provably exact): 10*|z_x|*|z|max < M - 60  =>  denom underflows vs EPS.
__global__ void __launch_bounds__(256)
k_rows(const float* __restrict__ z1, const float* __restrict__ z2) {
    __shared__ float zrow[8][64];
    int tid = threadIdx.x;
    int wib = tid >> 5, lane = tid & 31;
    int r = blockIdx.x * 8 + wib;
    if (r >= 65504) return;

    // decode r -> (l, b, x)
    int l = 0, T = TTOP;
    while (r >= 16 * T) { r -= 16 * T; ++l; T >>= 1; }
    int b = r / T;
    int x = r - b * T;
    int idx = rowOff(l) * 16 + b * T + x;

    float nx = g_norm[idx];
    float Mten = g_M[l * 16 + b];
    float rhs = Mten - 60.f;
    // skip iff rhs>0 and 10*nx*Mten < rhs^2  (<=> 10|z_x||z|max < M-60)
    if (rhs > 0.f && 10.f * nx * Mten < rhs * rhs) {
        if (lane == 0) { g_row_m[idx] = -1e30f; g_row_d[idx] = 0.f; }
        return;
    }

    const float* zb = lvl_base(l, b, z1, z2);
    float* zx = zrow[wib];
    zx[lane] = zb[(size_t)x * CDIM + lane];
    zx[lane + 32] = zb[(size_t)x * CDIM + 32 + lane];
    __syncwarp();

    float m = -FLT_MAX, d = 0.f;
    for (int y = x + 1 + lane; y < T; y += 32) {
        const float4* ry = reinterpret_cast<const float4*>(zb + (size_t)y * CDIM);
        float acc = 0.f;
#pragma unroll
        for (int k = 0; k < 16; k++) {
            float4 v = ry[k];
            acc += v.x * zx[4 * k] + v.y * zx[4 * k + 1] +
                   v.z * zx[4 * k + 2] + v.w * zx[4 * k + 3];
        }
        if (acc > m) { d = d * __expf(10.f * (m - acc)) + 1.f; m = acc; }
        else         { d += __expf(10.f * (acc - m)); }
    }
#pragma unroll
    for (int o = 16; o > 0; o >>= 1) {
        float mo = __shfl_down_sync(0xffffffffu, m, o);
        float dd = __shfl_down_sync(0xffffffffu, d, o);
        if (mo > m) { d = d * __expf(10.f * (m - mo)) + dd; m = mo; }
        else        { d += dd * __expf(10.f * (mo - m)); }
    }
    if (lane == 0) {
        g_row_m[idx] = fmaxf(10.f * m, -1e30f);
        g_row_d[idx] = d;
    }
}

// ---------------------------------------------------------------------------
// Instance loss via tf32 mma: one warp per slice, 4 warps/block.
__global__ void __launch_bounds__(128)
k_inst(const float* __restrict__ z1, const float* __restrict__ z2) {
    __shared__ float4 apack[4][8 * 36];
    __shared__ float2 bpack[4][16 * 36];
    __shared__ double wres[4];
    int tid = threadIdx.x;
    int w = tid >> 5, lid = tid & 31;
    int gq = lid >> 2, t4 = lid & 3;
    int slice = blockIdx.x * 4 + w;
    double myres = 0.0;

    if (slice < 4095) {
        int l = 0, T = TTOP, tt = slice;
        while (tt >= T) { tt -= T; ++l; T >>= 1; }

#pragma unroll
        for (int i = 0; i < 2; i++) {
            int task = lid + 32 * i;
            int rp = task >> 3, s = task & 7;
            const float* pa = lvl_base(l, rp, z1, z2) + (size_t)tt * CDIM + 8 * s;
            const float* pb = lvl_base(l, rp + 8, z1, z2) + (size_t)tt * CDIM + 8 * s;
            float4 u0 = tf32r4(*reinterpret_cast<const float4*>(pa));
            float4 u1 = tf32r4(*reinterpret_cast<const float4*>(pa + 4));
            float4 v0 = tf32r4(*reinterpret_cast<const float4*>(pb));
            float4 v1 = tf32r4(*reinterpret_cast<const float4*>(pb + 4));
            float4* ap = &apack[w][rp * 36 + s * 4];
            ap[0] = make_float4(u0.x, v0.x, u1.x, v1.x);
            ap[1] = make_float4(u0.y, v0.y, u1.y, v1.y);
            ap[2] = make_float4(u0.z, v0.z, u1.z, v1.z);
            ap[3] = make_float4(u0.w, v0.w, u1.w, v1.w);
            float2* bp0 = &bpack[w][rp * 36 + s * 4];
            bp0[0] = make_float2(u0.x, u1.x);
            bp0[1] = make_float2(u0.y, u1.y);
            bp0[2] = make_float2(u0.z, u1.z);
            bp0[3] = make_float2(u0.w, u1.w);
            float2* bp1 = &bpack[w][(rp + 8) * 36 + s * 4];
            bp1[0] = make_float2(v0.x, v1.x);
            bp1[1] = make_float2(v0.y, v1.y);
            bp1[2] = make_float2(v0.z, v1.z);
            bp1[3] = make_float2(v0.w, v1.w);
        }
        __syncwarp();

        float acc0[4] = {0.f, 0.f, 0.f, 0.f};
        float acc1[4] = {0.f, 0.f, 0.f, 0.f};
#pragma unroll
        for (int s = 0; s < 8; s++) {
            float4 a = apack[w][gq * 36 + s * 4 + t4];
            float2 b0 = bpack[w][gq * 36 + s * 4 + t4];
            float2 b1 = bpack[w][(8 + gq) * 36 + s * 4 + t4];
            mma_tf32(acc0, __float_as_uint(a.x), __float_as_uint(a.y),
                     __float_as_uint(a.z), __float_as_uint(a.w),
                     __float_as_uint(b0.x), __float_as_uint(b0.y));
            mma_tf32(acc1, __float_as_uint(a.x), __float_as_uint(a.y),
                     __float_as_uint(a.z), __float_as_uint(a.w),
                     __float_as_uint(b1.x), __float_as_uint(b1.y));
        }

        int j0 = 2 * t4, j1 = 2 * t4 + 1;
        float vA0 = (j0 == gq) ? -FLT_MAX : acc0[0];
        float vA1 = (j1 == gq) ? -FLT_MAX : acc0[1];
        float vA2 = acc1[0], vA3 = acc1[1];
        float vB0 = acc0[2], vB1 = acc0[3];
        float vB2 = (j0 == gq) ? -FLT_MAX : acc1[2];
        float vB3 = (j1 == gq) ? -FLT_MAX : acc1[3];

        float mA = fmaxf(fmaxf(vA0, vA1), fmaxf(vA2, vA3));
        float mB = fmaxf(fmaxf(vB0, vB1), fmaxf(vB2, vB3));
        mA = fmaxf(mA, __shfl_xor_sync(0xffffffffu, mA, 1));
        mA = fmaxf(mA, __shfl_xor_sync(0xffffffffu, mA, 2));
        mB = fmaxf(mB, __shfl_xor_sync(0xffffffffu, mB, 1));
        mB = fmaxf(mB, __shfl_xor_sync(0xffffffffu, mB, 2));

        float eA = __expf(vA0 - mA) + __expf(vA1 - mA) +
                   __expf(vA2 - mA) + __expf(vA3 - mA);
        float eB = __expf(vB0 - mB) + __expf(vB1 - mB) +
                   __expf(vB2 - mB) + __expf(vB3 - mB);
        eA += __shfl_xor_sync(0xffffffffu, eA, 1);
        eA += __shfl_xor_sync(0xffffffffu, eA, 2);
        eB += __shfl_xor_sync(0xffffffffu, eB, 1);
        eB += __shfl_xor_sync(0xffffffffu, eB, 2);

        float pA = ((j0 == gq) ? acc1[0] : 0.f) + ((j1 == gq) ? acc1[1] : 0.f);
        float pB = ((j0 == gq) ? acc0[2] : 0.f) + ((j1 == gq) ? acc0[3] : 0.f);
        pA += __shfl_xor_sync(0xffffffffu, pA, 1);
        pA += __shfl_xor_sync(0xffffffffu, pA, 2);
        pB += __shfl_xor_sync(0xffffffffu, pB, 1);
        pB += __shfl_xor_sync(0xffffffffu, pB, 2);

        float v = (mA + __logf(eA) - pA) + (mB + __logf(eB) - pB);
        v = (t4 == 0) ? v : 0.f;
#pragma unroll
        for (int o = 16; o > 0; o >>= 1)
            v += __shfl_down_sync(0xffffffffu, v, o);
        if (lid == 0) myres = (double)v / (384.0 * (double)T);
    }
    if (lid == 0) wres[w] = myres;
    __syncthreads();
    if (tid == 0) {
        double tot = 0.0;
#pragma unroll
        for (int q = 0; q < 4; q++) tot += wres[q];
        atomicAdd(&g_acc, tot);
    }
}

// ---------------------------------------------------------------------------
// Temporal kernel B: per (level,b) — M = max(10|z|^2, row maxes),
// sum_x (T-1-x)*(M + log(d_x e^{m_x-M} + eps)) minus closed-form sum of sims.
__global__ void __launch_bounds__(256)
k_tempB(const float* __restrict__ z1, const float* __restrict__ z2) {
    int b = blockIdx.x;
    int l = blockIdx.y;
    int T = TTOP >> l;
    const float* zb = lvl_base(l, b, z1, z2);
    int base = rowOff(l) * 16 + b * T;
    int tid = threadIdx.x;

    __shared__ float smax[256];
    __shared__ double sd[256];
    __shared__ float svec[4][64];

    float mloc = -FLT_MAX;
    float nrmp = 0.f;
    for (int x = tid; x < T; x += 256) {
        float nrm = g_norm[base + x];
        mloc = fmaxf(mloc, fmaxf(nrm * 10.0f, g_row_m[base + x]));
        nrmp += nrm;
    }
    smax[tid] = mloc;
    sd[tid] = (double)nrmp;

    {
        int c = tid & 63, rg = tid >> 6;
        float vs = 0.f;
        for (int x = rg; x < T; x += 4) vs += zb[(size_t)x * CDIM + c];
        svec[rg][c] = vs;
    }
    __syncthreads();
    for (int s = 128; s > 0; s >>= 1) {
        if (tid < s) {
            smax[tid] = fmaxf(smax[tid], smax[tid + s]);
            sd[tid] += sd[tid + s];
        }
        __syncthreads();
    }
    float M = smax[0];
    double nrmtot = sd[0];
    __syncthreads();

    double s2 = 0.0;
    if (tid < 64) {
        float S = svec[0][tid] + svec[1][tid] + svec[2][tid] + svec[3][tid];
        s2 = (double)S * (double)S;
    }
    sd[tid] = s2;
    __syncthreads();
    for (int s = 128; s > 0; s >>= 1) {
        if (tid < s) sd[tid] += sd[tid + s];
        __syncthreads();
    }
    double S2 = sd[0];
    __syncthreads();

    double sum = 0.0;
    for (int x = tid; x < T; x += 256) {
        float mrow = g_row_m[base + x];
        float drow = g_row_d[base + x];
        float dg = drow * expf(mrow - M);
        float valrow = M + logf(dg + 1e-5f);
        sum += (double)(T - 1 - x) * (double)valrow;
    }
    sd[tid] = sum;
    __syncthreads();
    for (int s = 128; s > 0; s >>= 1) {
        if (tid < s) sd[tid] += sd[tid + s];
        __syncthreads();
    }
    if (tid == 0) {
        double Ssum = 5.0 * (S2 - nrmtot);
        double wgt = 1.0 / (192.0 * (double)T * (double)(T - 1));
        atomicAdd(&g_acc, wgt * (sd[0] - Ssum));
    }
}

__global__ void k_fin(float* out) { out[0] = (float)g_acc; }

// ---------------------------------------------------------------------------
extern "C" void kernel_launch(void* const* d_in, const int* in_sizes, int n_in,
                              void* d_out, int out_size) {
    const float* z1 = (const float*)d_in[0];
    const float* z2 = (const float*)d_in[1];
    float* out = (float*)d_out;

    {
        int n = 2 * 512 * 2016;
        k_poolA<<<(n + 255) / 256, 256>>>(z1, z2);
    }
    {
        int n = 2 * 512 * 31;
        k_poolB<<<(n + 255) / 256, 256>>>();
    }

    k_norm<<<dim3(16, 11), 256>>>(z1, z2);   // also zeroes g_acc
    k_inst<<<1024, 128>>>(z1, z2);
    k_rows<<<(65504 + 7) / 8, 256>>>(z1, z2);
    k_tempB<<<dim3(16, 11), 256>>>(z1, z2);

    k_fin<<<1, 1>>>(out);
}

// round 10
// speedup vs baseline: 3.2547x; 1.1272x over previous
#include <cuda_runtime.h>
#include <cstdint>
#include <float.h>
#include <math.h>

// ---------------------------------------------------------------------------
// TS2Vec hierarchical loss, B=8, T=2048, C=64, ALPHA=0.5, TAU=0.1, EPS=1e-5
// Round 10: k_rows fallback rebuilt with coalesced smem staging (the round-9
// version paid ~32 L1 wavefronts per LDG on lane-strided row loads).
// Temporal Gram remains eliminated via the Cauchy-Schwarz underflow proof.
// ---------------------------------------------------------------------------

#define TTOP 2048
#define CDIM 64

__device__ double g_acc;
__device__ __align__(16) float g_pyr[2][8 * 2047 * 64];   // pooled levels 1..11
__device__ float g_row_m[4094 * 16];                       // per-row max (s-units)
__device__ float g_row_d[4094 * 16];                       // per-row denom
__device__ float g_norm[4094 * 16];                        // per-row |z|^2
__device__ float g_M[11 * 16];                             // per (l,b): 10*max|z|^2

__device__ __forceinline__ int pyrOff(int l) { return 512 * (2048 - (4096 >> l)); }
__device__ __forceinline__ int rowOff(int l) { return 4096 - (4096 >> l); }
__device__ __forceinline__ const float* lvl_base(int l, int b,
                                                 const float* z1, const float* z2) {
    int bb = b & 7;
    const float* z = (b < 8) ? z1 : z2;
    const float* p = (b < 8) ? g_pyr[0] : g_pyr[1];
    if (l == 0) return z + (size_t)bb * TTOP * CDIM;
    return p + pyrOff(l) + (size_t)bb * (size_t)(TTOP >> l) * CDIM;
}

__device__ __forceinline__ float tf32r(float x) {
    uint32_t r;
    asm("cvt.rna.tf32.f32 %0, %1;" : "=r"(r) : "f"(x));
    return __uint_as_float(r);
}
__device__ __forceinline__ float4 tf32r4(float4 v) {
    return make_float4(tf32r(v.x), tf32r(v.y), tf32r(v.z), tf32r(v.w));
}

__device__ __forceinline__ void mma_tf32(float c[4], uint32_t a0, uint32_t a1,
                                         uint32_t a2, uint32_t a3,
                                         uint32_t b0, uint32_t b1) {
    asm volatile(
        "mma.sync.aligned.m16n8k8.row.col.f32.tf32.tf32.f32 "
        "{%0,%1,%2,%3}, {%4,%5,%6,%7}, {%8,%9}, {%0,%1,%2,%3};"
        : "+f"(c[0]), "+f"(c[1]), "+f"(c[2]), "+f"(c[3])
        : "r"(a0), "r"(a1), "r"(a2), "r"(a3), "r"(b0), "r"(b1));
}

// ---------------------------------------------------------------------------
__global__ void k_poolA(const float* __restrict__ z1, const float* __restrict__ z2) {
    int idx = blockIdx.x * blockDim.x + threadIdx.x;
    const int NPER = 512 * 2016;
    if (idx >= 2 * NPER) return;
    int tensor = (idx >= NPER) ? 1 : 0;
    int off = idx - tensor * NPER;
    const float* in = tensor ? z2 : z1;
    int l = 1, T = 1024;
    while (off >= 512 * T) { off -= 512 * T; ++l; T >>= 1; }
    int c = off & 63;
    int t = (off >> 6) % T;
    int b = (off >> 6) / T;
    int w = TTOP / T;
    const float* src = in + ((size_t)b * TTOP + (size_t)t * w) * CDIM + c;
    float m = src[0];
    for (int k = 1; k < w; k++) m = fmaxf(m, src[(size_t)k * CDIM]);
    g_pyr[tensor][pyrOff(l) + ((size_t)b * T + t) * CDIM + c] = m;
}

__global__ void k_poolB() {
    int idx = blockIdx.x * blockDim.x + threadIdx.x;
    const int NPER = 512 * 31;
    if (idx >= 2 * NPER) return;
    int tensor = (idx >= NPER) ? 1 : 0;
    int off = idx - tensor * NPER;
    int l = 7, T = 16;
    while (off >= 512 * T) { off -= 512 * T; ++l; T >>= 1; }
    int c = off & 63;
    int t = (off >> 6) % T;
    int b = (off >> 6) / T;
    int w = 32 / T;
    const float* src = g_pyr[tensor] + pyrOff(6) + ((size_t)b * 32 + (size_t)t * w) * CDIM + c;
    float m = src[0];
    for (int k = 1; k < w; k++) m = fmaxf(m, src[(size_t)k * CDIM]);
    g_pyr[tensor][pyrOff(l) + ((size_t)b * T + t) * CDIM + c] = m;
}

// ---------------------------------------------------------------------------
// Row norms + per-(l,b) scaled max diag. Also zeroes g_acc.
__global__ void __launch_bounds__(256)
k_norm(const float* __restrict__ z1, const float* __restrict__ z2) {
    int b = blockIdx.x;          // 0..15
    int l = blockIdx.y;          // 0..10
    int T = TTOP >> l;
    const float* zb = lvl_base(l, b, z1, z2);
    int base = rowOff(l) * 16 + b * T;
    int tid = threadIdx.x;
    if (b == 0 && l == 0 && tid == 0) g_acc = 0.0;

    __shared__ float smax[256];
    float mx = 0.f;
    for (int x = tid; x < T; x += 256) {
        const float4* row = reinterpret_cast<const float4*>(zb + (size_t)x * CDIM);
        float nrm = 0.f;
#pragma unroll
        for (int c = 0; c < 16; c++) {
            float4 v = row[c];
            nrm += v.x * v.x + v.y * v.y + v.z * v.z + v.w * v.w;
        }
        g_norm[base + x] = nrm;
        mx = fmaxf(mx, nrm);
    }
    smax[tid] = mx;
    __syncthreads();
    for (int s = 128; s > 0; s >>= 1) {
        if (tid < s) smax[tid] = fmaxf(smax[tid], smax[tid + s]);
        __syncthreads();
    }
    if (tid == 0) g_M[l * 16 + b] = 10.f * smax[0];
}

// ---------------------------------------------------------------------------
// Per-row flag test + sparse exact fallback. One warp per row; y rows staged
// into smem COALESCED in 32-row chunks, dot from smem (conflict-free, pitch 65).
// Skip (provably exact): 10*|z_x|*|z|max < M - 60  =>  denom underflows vs EPS.
#define YB_PITCH 65
__global__ void __launch_bounds__(128)
k_rows(const float* __restrict__ z1, const float* __restrict__ z2) {
    __shared__ float ybuf[4][32][YB_PITCH];   // 33.3 KB
    __shared__ float zxbuf[4][66];
    int tid = threadIdx.x;
    int wib = tid >> 5, lane = tid & 31;
    int r = blockIdx.x * 4 + wib;
    if (r >= 65504) return;

    // decode r -> (l, b, x)
    int l = 0, T = TTOP;
    while (r >= 16 * T) { r -= 16 * T; ++l; T >>= 1; }
    int b = r / T;
    int x = r - b * T;
    int idx = rowOff(l) * 16 + b * T + x;

    float nx = g_norm[idx];
    float Mten = g_M[l * 16 + b];
    float rhs = Mten - 60.f;
    if (rhs > 0.f && 10.f * nx * Mten < rhs * rhs) {
        if (lane == 0) { g_row_m[idx] = -1e30f; g_row_d[idx] = 0.f; }
        return;
    }

    const float* zb = lvl_base(l, b, z1, z2);
    float* zx = zxbuf[wib];
    zx[lane] = zb[(size_t)x * CDIM + lane];
    zx[lane + 32] = zb[(size_t)x * CDIM + 32 + lane];
    __syncwarp();

    float m = -FLT_MAX, d = 0.f;
    int y0 = ((x + 1) >> 5) << 5;                 // first 32-chunk containing y>x
    for (int ys = y0; ys < T; ys += 32) {
        // stage rows ys..ys+31: 512 float4 tasks, 16/lane, coalesced per row
#pragma unroll
        for (int q = 0; q < 16; q++) {
            int task = q * 32 + lane;
            int row = task >> 4;                  // 0..31
            int c4 = task & 15;
            int y = ys + row;
            float4 v = make_float4(0.f, 0.f, 0.f, 0.f);
            if (y < T)
                v = *reinterpret_cast<const float4*>(zb + (size_t)y * CDIM + 4 * c4);
            float* dst = &ybuf[wib][row][4 * c4];
            dst[0] = v.x; dst[1] = v.y; dst[2] = v.z; dst[3] = v.w;
        }
        __syncwarp();
        int y = ys + lane;
        if (y > x && y < T) {
            const float* ry = ybuf[wib][lane];
            float acc = 0.f;
#pragma unroll
            for (int k = 0; k < 64; k++) acc += zx[k] * ry[k];
            if (acc > m)             { d = d * __expf(10.f * (m - acc)) + 1.f; m = acc; }
            else if (acc > m - 2.5f) { d += __expf(10.f * (acc - m)); }
        }
        __syncwarp();
    }

#pragma unroll
    for (int o = 16; o > 0; o >>= 1) {
        float mo = __shfl_down_sync(0xffffffffu, m, o);
        float dd = __shfl_down_sync(0xffffffffu, d, o);
        if (mo > m) { d = d * __expf(10.f * (m - mo)) + dd; m = mo; }
        else        { d += dd * __expf(10.f * (mo - m)); }
    }
    if (lane == 0) {
        g_row_m[idx] = fmaxf(10.f * m, -1e30f);
        g_row_d[idx] = d;
    }
}

// ---------------------------------------------------------------------------
// Instance loss via tf32 mma: one warp per slice, 4 warps/block.
__global__ void __launch_bounds__(128)
k_inst(const float* __restrict__ z1, const float* __restrict__ z2) {
    __shared__ float4 apack[4][8 * 36];
    __shared__ float2 bpack[4][16 * 36];
    __shared__ double wres[4];
    int tid = threadIdx.x;
    int w = tid >> 5, lid = tid & 31;
    int gq = lid >> 2, t4 = lid & 3;
    int slice = blockIdx.x * 4 + w;
    double myres = 0.0;

    if (slice < 4095) {
        int l = 0, T = TTOP, tt = slice;
        while (tt >= T) { tt -= T; ++l; T >>= 1; }

#pragma unroll
        for (int i = 0; i < 2; i++) {
            int task = lid + 32 * i;
            int rp = task >> 3, s = task & 7;
            const float* pa = lvl_base(l, rp, z1, z2) + (size_t)tt * CDIM + 8 * s;
            const float* pb = lvl_base(l, rp + 8, z1, z2) + (size_t)tt * CDIM + 8 * s;
            float4 u0 = tf32r4(*reinterpret_cast<const float4*>(pa));
            float4 u1 = tf32r4(*reinterpret_cast<const float4*>(pa + 4));
            float4 v0 = tf32r4(*reinterpret_cast<const float4*>(pb));
            float4 v1 = tf32r4(*reinterpret_cast<const float4*>(pb + 4));
            float4* ap = &apack[w][rp * 36 + s * 4];
            ap[0] = make_float4(u0.x, v0.x, u1.x, v1.x);
            ap[1] = make_float4(u0.y, v0.y, u1.y, v1.y);
            ap[2] = make_float4(u0.z, v0.z, u1.z, v1.z);
            ap[3] = make_float4(u0.w, v0.w, u1.w, v1.w);
            float2* bp0 = &bpack[w][rp * 36 + s * 4];
            bp0[0] = make_float2(u0.x, u1.x);
            bp0[1] = make_float2(u0.y, u1.y);
            bp0[2] = make_float2(u0.z, u1.z);
            bp0[3] = make_float2(u0.w, u1.w);
            float2* bp1 = &bpack[w][(rp + 8) * 36 + s * 4];
            bp1[0] = make_float2(v0.x, v1.x);
            bp1[1] = make_float2(v0.y, v1.y);
            bp1[2] = make_float2(v0.z, v1.z);
            bp1[3] = make_float2(v0.w, v1.w);
        }
        __syncwarp();

        float acc0[4] = {0.f, 0.f, 0.f, 0.f};
        float acc1[4] = {0.f, 0.f, 0.f, 0.f};
#pragma unroll
        for (int s = 0; s < 8; s++) {
            float4 a = apack[w][gq * 36 + s * 4 + t4];
            float2 b0 = bpack[w][gq * 36 + s * 4 + t4];
            float2 b1 = bpack[w][(8 + gq) * 36 + s * 4 + t4];
            mma_tf32(acc0, __float_as_uint(a.x), __float_as_uint(a.y),
                     __float_as_uint(a.z), __float_as_uint(a.w),
                     __float_as_uint(b0.x), __float_as_uint(b0.y));
            mma_tf32(acc1, __float_as_uint(a.x), __float_as_uint(a.y),
                     __float_as_uint(a.z), __float_as_uint(a.w),
                     __float_as_uint(b1.x), __float_as_uint(b1.y));
        }

        int j0 = 2 * t4, j1 = 2 * t4 + 1;
        float vA0 = (j0 == gq) ? -FLT_MAX : acc0[0];
        float vA1 = (j1 == gq) ? -FLT_MAX : acc0[1];
        float vA2 = acc1[0], vA3 = acc1[1];
        float vB0 = acc0[2], vB1 = acc0[3];
        float vB2 = (j0 == gq) ? -FLT_MAX : acc1[2];
        float vB3 = (j1 == gq) ? -FLT_MAX : acc1[3];

        float mA = fmaxf(fmaxf(vA0, vA1), fmaxf(vA2, vA3));
        float mB = fmaxf(fmaxf(vB0, vB1), fmaxf(vB2, vB3));
        mA = fmaxf(mA, __shfl_xor_sync(0xffffffffu, mA, 1));
        mA = fmaxf(mA, __shfl_xor_sync(0xffffffffu, mA, 2));
        mB = fmaxf(mB, __shfl_xor_sync(0xffffffffu, mB, 1));
        mB = fmaxf(mB, __shfl_xor_sync(0xffffffffu, mB, 2));

        float eA = __expf(vA0 - mA) + __expf(vA1 - mA) +
                   __expf(vA2 - mA) + __expf(vA3 - mA);
        float eB = __expf(vB0 - mB) + __expf(vB1 - mB) +
                   __expf(vB2 - mB) + __expf(vB3 - mB);
        eA += __shfl_xor_sync(0xffffffffu, eA, 1);
        eA += __shfl_xor_sync(0xffffffffu, eA, 2);
        eB += __shfl_xor_sync(0xffffffffu, eB, 1);
        eB += __shfl_xor_sync(0xffffffffu, eB, 2);

        float pA = ((j0 == gq) ? acc1[0] : 0.f) + ((j1 == gq) ? acc1[1] : 0.f);
        float pB = ((j0 == gq) ? acc0[2] : 0.f) + ((j1 == gq) ? acc0[3] : 0.f);
        pA += __shfl_xor_sync(0xffffffffu, pA, 1);
        pA += __shfl_xor_sync(0xffffffffu, pA, 2);
        pB += __shfl_xor_sync(0xffffffffu, pB, 1);
        pB += __shfl_xor_sync(0xffffffffu, pB, 2);

        float v = (mA + __logf(eA) - pA) + (mB + __logf(eB) - pB);
        v = (t4 == 0) ? v : 0.f;
#pragma unroll
        for (int o = 16; o > 0; o >>= 1)
            v += __shfl_down_sync(0xffffffffu, v, o);
        if (lid == 0) myres = (double)v / (384.0 * (double)T);
    }
    if (lid == 0) wres[w] = myres;
    __syncthreads();
    if (tid == 0) {
        double tot = 0.0;
#pragma unroll
        for (int q = 0; q < 4; q++) tot += wres[q];
        atomicAdd(&g_acc, tot);
    }
}

// ---------------------------------------------------------------------------
// Temporal kernel B: per (level,b) — M = max(10|z|^2, row maxes),
// sum_x (T-1-x)*(M + log(d_x e^{m_x-M} + eps)) minus closed-form sum of sims.
__global__ void __launch_bounds__(256)
k_tempB(const float* __restrict__ z1, const float* __restrict__ z2) {
    int b = blockIdx.x;
    int l = blockIdx.y;
    int T = TTOP >> l;
    const float* zb = lvl_base(l, b, z1, z2);
    int base = rowOff(l) * 16 + b * T;
    int tid = threadIdx.x;

    __shared__ float smax[256];
    __shared__ double sd[256];
    __shared__ float svec[4][64];

    float mloc = -FLT_MAX;
    float nrmp = 0.f;
    for (int x = tid; x < T; x += 256) {
        float nrm = g_norm[base + x];
        mloc = fmaxf(mloc, fmaxf(nrm * 10.0f, g_row_m[base + x]));
        nrmp += nrm;
    }
    smax[tid] = mloc;
    sd[tid] = (double)nrmp;

    {
        int c = tid & 63, rg = tid >> 6;
        float vs = 0.f;
        for (int x = rg; x < T; x += 4) vs += zb[(size_t)x * CDIM + c];
        svec[rg][c] = vs;
    }
    __syncthreads();
    for (int s = 128; s > 0; s >>= 1) {
        if (tid < s) {
            smax[tid] = fmaxf(smax[tid], smax[tid + s]);
            sd[tid] += sd[tid + s];
        }
        __syncthreads();
    }
    float M = smax[0];
    double nrmtot = sd[0];
    __syncthreads();

    double s2 = 0.0;
    if (tid < 64) {
        float S = svec[0][tid] + svec[1][tid] + svec[2][tid] + svec[3][tid];
        s2 = (double)S * (double)S;
    }
    sd[tid] = s2;
    __syncthreads();
    for (int s = 128; s > 0; s >>= 1) {
        if (tid < s) sd[tid] += sd[tid + s];
        __syncthreads();
    }
    double S2 = sd[0];
    __syncthreads();

    double sum = 0.0;
    for (int x = tid; x < T; x += 256) {
        float mrow = g_row_m[base + x];
        float drow = g_row_d[base + x];
        float dg = drow * expf(mrow - M);
        float valrow = M + logf(dg + 1e-5f);
        sum += (double)(T - 1 - x) * (double)valrow;
    }
    sd[tid] = sum;
    __syncthreads();
    for (int s = 128; s > 0; s >>= 1) {
        if (tid < s) sd[tid] += sd[tid + s];
        __syncthreads();
    }
    if (tid == 0) {
        double Ssum = 5.0 * (S2 - nrmtot);
        double wgt = 1.0 / (192.0 * (double)T * (double)(T - 1));
        atomicAdd(&g_acc, wgt * (sd[0] - Ssum));
    }
}

__global__ void k_fin(float* out) { out[0] = (float)g_acc; }

// ---------------------------------------------------------------------------
extern "C" void kernel_launch(void* const* d_in, const int* in_sizes, int n_in,
                              void* d_out, int out_size) {
    const float* z1 = (const float*)d_in[0];
    const float* z2 = (const float*)d_in[1];
    float* out = (float*)d_out;

    {
        int n = 2 * 512 * 2016;
        k_poolA<<<(n + 255) / 256, 256>>>(z1, z2);
    }
    {
        int n = 2 * 512 * 31;
        k_poolB<<<(n + 255) / 256, 256>>>();
    }

    k_norm<<<dim3(16, 11), 256>>>(z1, z2);   // also zeroes g_acc
    k_inst<<<1024, 128>>>(z1, z2);
    k_rows<<<(65504 + 3) / 4, 128>>>(z1, z2);
    k_tempB<<<dim3(16, 11), 256>>>(z1, z2);

    k_fin<<<1, 1>>>(out);
}

// round 11
// speedup vs baseline: 5.0528x; 1.5525x over previous
#include <cuda_runtime.h>
#include <cstdint>
#include <float.h>
#include <math.h>

// ---------------------------------------------------------------------------
// TS2Vec hierarchical loss, B=8, T=2048, C=64, ALPHA=0.5, TAU=0.1, EPS=1e-5
// Round 11: fallback reduced from O(flagged*T) to O(flagged^2):
//   a pair (x,y) can only beat the e^-60 underflow threshold if BOTH rows are
//   in the Cauchy-Schwarz flagged set, and with M = 10*max|z|^2 known exactly,
//   dg_x = sum exp(10*sim - M) accumulates directly (no online softmax).
// ---------------------------------------------------------------------------

#define TTOP 2048
#define CDIM 64

__device__ double g_acc;
__device__ __align__(16) float g_pyr[2][8 * 2047 * 64];   // pooled levels 1..11
__device__ float g_row_d[4094 * 16];                       // per-row dg (rel. M)
__device__ float g_norm[4094 * 16];                        // per-row |z|^2
__device__ float g_M[11 * 16];                             // per (l,b): 10*max|z|^2

__device__ __forceinline__ int pyrOff(int l) { return 512 * (2048 - (4096 >> l)); }
__device__ __forceinline__ int rowOff(int l) { return 4096 - (4096 >> l); }
__device__ __forceinline__ const float* lvl_base(int l, int b,
                                                 const float* z1, const float* z2) {
    int bb = b & 7;
    const float* z = (b < 8) ? z1 : z2;
    const float* p = (b < 8) ? g_pyr[0] : g_pyr[1];
    if (l == 0) return z + (size_t)bb * TTOP * CDIM;
    return p + pyrOff(l) + (size_t)bb * (size_t)(TTOP >> l) * CDIM;
}

__device__ __forceinline__ float tf32r(float x) {
    uint32_t r;
    asm("cvt.rna.tf32.f32 %0, %1;" : "=r"(r) : "f"(x));
    return __uint_as_float(r);
}
__device__ __forceinline__ float4 tf32r4(float4 v) {
    return make_float4(tf32r(v.x), tf32r(v.y), tf32r(v.z), tf32r(v.w));
}

__device__ __forceinline__ void mma_tf32(float c[4], uint32_t a0, uint32_t a1,
                                         uint32_t a2, uint32_t a3,
                                         uint32_t b0, uint32_t b1) {
    asm volatile(
        "mma.sync.aligned.m16n8k8.row.col.f32.tf32.tf32.f32 "
        "{%0,%1,%2,%3}, {%4,%5,%6,%7}, {%8,%9}, {%0,%1,%2,%3};"
        : "+f"(c[0]), "+f"(c[1]), "+f"(c[2]), "+f"(c[3])
        : "r"(a0), "r"(a1), "r"(a2), "r"(a3), "r"(b0), "r"(b1));
}

// ---------------------------------------------------------------------------
__global__ void k_poolA(const float* __restrict__ z1, const float* __restrict__ z2) {
    int idx = blockIdx.x * blockDim.x + threadIdx.x;
    const int NPER = 512 * 2016;
    if (idx >= 2 * NPER) return;
    int tensor = (idx >= NPER) ? 1 : 0;
    int off = idx - tensor * NPER;
    const float* in = tensor ? z2 : z1;
    int l = 1, T = 1024;
    while (off >= 512 * T) { off -= 512 * T; ++l; T >>= 1; }
    int c = off & 63;
    int t = (off >> 6) % T;
    int b = (off >> 6) / T;
    int w = TTOP / T;
    const float* src = in + ((size_t)b * TTOP + (size_t)t * w) * CDIM + c;
    float m = src[0];
    for (int k = 1; k < w; k++) m = fmaxf(m, src[(size_t)k * CDIM]);
    g_pyr[tensor][pyrOff(l) + ((size_t)b * T + t) * CDIM + c] = m;
}

__global__ void k_poolB() {
    int idx = blockIdx.x * blockDim.x + threadIdx.x;
    const int NPER = 512 * 31;
    if (idx >= 2 * NPER) return;
    int tensor = (idx >= NPER) ? 1 : 0;
    int off = idx - tensor * NPER;
    int l = 7, T = 16;
    while (off >= 512 * T) { off -= 512 * T; ++l; T >>= 1; }
    int c = off & 63;
    int t = (off >> 6) % T;
    int b = (off >> 6) / T;
    int w = 32 / T;
    const float* src = g_pyr[tensor] + pyrOff(6) + ((size_t)b * 32 + (size_t)t * w) * CDIM + c;
    float m = src[0];
    for (int k = 1; k < w; k++) m = fmaxf(m, src[(size_t)k * CDIM]);
    g_pyr[tensor][pyrOff(l) + ((size_t)b * T + t) * CDIM + c] = m;
}

// ---------------------------------------------------------------------------
// Row norms + per-(l,b) scaled max diag. Zeroes g_row_d and g_acc.
__global__ void __launch_bounds__(256)
k_norm(const float* __restrict__ z1, const float* __restrict__ z2) {
    int b = blockIdx.x;          // 0..15
    int l = blockIdx.y;          // 0..10
    int T = TTOP >> l;
    const float* zb = lvl_base(l, b, z1, z2);
    int base = rowOff(l) * 16 + b * T;
    int tid = threadIdx.x;
    if (b == 0 && l == 0 && tid == 0) g_acc = 0.0;

    __shared__ float smax[256];
    float mx = 0.f;
    for (int x = tid; x < T; x += 256) {
        const float4* row = reinterpret_cast<const float4*>(zb + (size_t)x * CDIM);
        float nrm = 0.f;
#pragma unroll
        for (int c = 0; c < 16; c++) {
            float4 v = row[c];
            nrm += v.x * v.x + v.y * v.y + v.z * v.z + v.w * v.w;
        }
        g_norm[base + x] = nrm;
        g_row_d[base + x] = 0.f;
        mx = fmaxf(mx, nrm);
    }
    smax[tid] = mx;
    __syncthreads();
    for (int s = 128; s > 0; s >>= 1) {
        if (tid < s) smax[tid] = fmaxf(smax[tid], smax[tid + s]);
        __syncthreads();
    }
    if (tid == 0) g_M[l * 16 + b] = 10.f * smax[0];
}

// ---------------------------------------------------------------------------
// Flagged-pair kernel: per (l,b), compact the Cauchy-Schwarz candidate set,
// then dg_x += exp(10*sim(x,y) - M) over candidate pairs y > x only.
#define NSTAGE 128
__global__ void __launch_bounds__(256)
k_pairs(const float* __restrict__ z1, const float* __restrict__ z2) {
    __shared__ int s_cnt;
    __shared__ int list[2048];
    __shared__ float zs[NSTAGE][65];
    int b = blockIdx.x;
    int l = blockIdx.y;
    int T = TTOP >> l;
    const float* zb = lvl_base(l, b, z1, z2);
    int base = rowOff(l) * 16 + b * T;
    int tid = threadIdx.x;

    if (tid == 0) s_cnt = 0;
    __syncthreads();

    float Mten = g_M[l * 16 + b];
    float rhs = Mten - 60.f;
    float thr2 = rhs * rhs;
    for (int x = tid; x < T; x += 256) {
        float nx = g_norm[base + x];
        bool skip = (rhs > 0.f) && (10.f * nx * Mten < thr2);
        if (!skip) { int p = atomicAdd(&s_cnt, 1); list[p] = x; }
    }
    __syncthreads();
    int n = s_cnt;
    if (n < 2) return;

    // stage first NSTAGE candidate rows into smem
    int nst = (n < NSTAGE) ? n : NSTAGE;
    for (int e = tid; e < nst * 16; e += 256) {
        int i = e >> 4, c4 = e & 15;
        float4 v = *reinterpret_cast<const float4*>(
            zb + (size_t)list[i] * CDIM + 4 * c4);
        float* dst = &zs[i][4 * c4];
        dst[0] = v.x; dst[1] = v.y; dst[2] = v.z; dst[3] = v.w;
    }
    __syncthreads();

    for (int i = 0; i < n - 1; i++) {
        int xi = list[i];
        for (int jj = i + 1 + tid; jj < n; jj += 256) {
            int xj = list[jj];
            float acc = 0.f;
            if (i < NSTAGE && jj < NSTAGE) {
                const float* pi = zs[i];
                const float* pj = zs[jj];
#pragma unroll
                for (int k = 0; k < 64; k++) acc += pi[k] * pj[k];
            } else {
                const float* pi = zb + (size_t)xi * CDIM;
                const float* pj = zb + (size_t)xj * CDIM;
#pragma unroll
                for (int k = 0; k < 64; k++) acc += pi[k] * pj[k];
            }
            float s = 10.f * acc - Mten;
            if (s > -70.f) {
                int xlo = (xi < xj) ? xi : xj;
                atomicAdd(&g_row_d[base + xlo], __expf(s));
            }
        }
    }
}

// ---------------------------------------------------------------------------
// Instance loss via tf32 mma: one warp per slice, 4 warps/block.
__global__ void __launch_bounds__(128)
k_inst(const float* __restrict__ z1, const float* __restrict__ z2) {
    __shared__ float4 apack[4][8 * 36];
    __shared__ float2 bpack[4][16 * 36];
    __shared__ double wres[4];
    int tid = threadIdx.x;
    int w = tid >> 5, lid = tid & 31;
    int gq = lid >> 2, t4 = lid & 3;
    int slice = blockIdx.x * 4 + w;
    double myres = 0.0;

    if (slice < 4095) {
        int l = 0, T = TTOP, tt = slice;
        while (tt >= T) { tt -= T; ++l; T >>= 1; }

#pragma unroll
        for (int i = 0; i < 2; i++) {
            int task = lid + 32 * i;
            int rp = task >> 3, s = task & 7;
            const float* pa = lvl_base(l, rp, z1, z2) + (size_t)tt * CDIM + 8 * s;
            const float* pb = lvl_base(l, rp + 8, z1, z2) + (size_t)tt * CDIM + 8 * s;
            float4 u0 = tf32r4(*reinterpret_cast<const float4*>(pa));
            float4 u1 = tf32r4(*reinterpret_cast<const float4*>(pa + 4));
            float4 v0 = tf32r4(*reinterpret_cast<const float4*>(pb));
            float4 v1 = tf32r4(*reinterpret_cast<const float4*>(pb + 4));
            float4* ap = &apack[w][rp * 36 + s * 4];
            ap[0] = make_float4(u0.x, v0.x, u1.x, v1.x);
            ap[1] = make_float4(u0.y, v0.y, u1.y, v1.y);
            ap[2] = make_float4(u0.z, v0.z, u1.z, v1.z);
            ap[3] = make_float4(u0.w, v0.w, u1.w, v1.w);
            float2* bp0 = &bpack[w][rp * 36 + s * 4];
            bp0[0] = make_float2(u0.x, u1.x);
            bp0[1] = make_float2(u0.y, u1.y);
            bp0[2] = make_float2(u0.z, u1.z);
            bp0[3] = make_float2(u0.w, u1.w);
            float2* bp1 = &bpack[w][(rp + 8) * 36 + s * 4];
            bp1[0] = make_float2(v0.x, v1.x);
            bp1[1] = make_float2(v0.y, v1.y);
            bp1[2] = make_float2(v0.z, v1.z);
            bp1[3] = make_float2(v0.w, v1.w);
        }
        __syncwarp();

        float acc0[4] = {0.f, 0.f, 0.f, 0.f};
        float acc1[4] = {0.f, 0.f, 0.f, 0.f};
#pragma unroll
        for (int s = 0; s < 8; s++) {
            float4 a = apack[w][gq * 36 + s * 4 + t4];
            float2 b0 = bpack[w][gq * 36 + s * 4 + t4];
            float2 b1 = bpack[w][(8 + gq) * 36 + s * 4 + t4];
            mma_tf32(acc0, __float_as_uint(a.x), __float_as_uint(a.y),
                     __float_as_uint(a.z), __float_as_uint(a.w),
                     __float_as_uint(b0.x), __float_as_uint(b0.y));
            mma_tf32(acc1, __float_as_uint(a.x), __float_as_uint(a.y),
                     __float_as_uint(a.z), __float_as_uint(a.w),
                     __float_as_uint(b1.x), __float_as_uint(b1.y));
        }

        int j0 = 2 * t4, j1 = 2 * t4 + 1;
        float vA0 = (j0 == gq) ? -FLT_MAX : acc0[0];
        float vA1 = (j1 == gq) ? -FLT_MAX : acc0[1];
        float vA2 = acc1[0], vA3 = acc1[1];
        float vB0 = acc0[2], vB1 = acc0[3];
        float vB2 = (j0 == gq) ? -FLT_MAX : acc1[2];
        float vB3 = (j1 == gq) ? -FLT_MAX : acc1[3];

        float mA = fmaxf(fmaxf(vA0, vA1), fmaxf(vA2, vA3));
        float mB = fmaxf(fmaxf(vB0, vB1), fmaxf(vB2, vB3));
        mA = fmaxf(mA, __shfl_xor_sync(0xffffffffu, mA, 1));
        mA = fmaxf(mA, __shfl_xor_sync(0xffffffffu, mA, 2));
        mB = fmaxf(mB, __shfl_xor_sync(0xffffffffu, mB, 1));
        mB = fmaxf(mB, __shfl_xor_sync(0xffffffffu, mB, 2));

        float eA = __expf(vA0 - mA) + __expf(vA1 - mA) +
                   __expf(vA2 - mA) + __expf(vA3 - mA);
        float eB = __expf(vB0 - mB) + __expf(vB1 - mB) +
                   __expf(vB2 - mB) + __expf(vB3 - mB);
        eA += __shfl_xor_sync(0xffffffffu, eA, 1);
        eA += __shfl_xor_sync(0xffffffffu, eA, 2);
        eB += __shfl_xor_sync(0xffffffffu, eB, 1);
        eB += __shfl_xor_sync(0xffffffffu, eB, 2);

        float pA = ((j0 == gq) ? acc1[0] : 0.f) + ((j1 == gq) ? acc1[1] : 0.f);
        float pB = ((j0 == gq) ? acc0[2] : 0.f) + ((j1 == gq) ? acc0[3] : 0.f);
        pA += __shfl_xor_sync(0xffffffffu, pA, 1);
        pA += __shfl_xor_sync(0xffffffffu, pA, 2);
        pB += __shfl_xor_sync(0xffffffffu, pB, 1);
        pB += __shfl_xor_sync(0xffffffffu, pB, 2);

        float v = (mA + __logf(eA) - pA) + (mB + __logf(eB) - pB);
        v = (t4 == 0) ? v : 0.f;
#pragma unroll
        for (int o = 16; o > 0; o >>= 1)
            v += __shfl_down_sync(0xffffffffu, v, o);
        if (lid == 0) myres = (double)v / (384.0 * (double)T);
    }
    if (lid == 0) wres[w] = myres;
    __syncthreads();
    if (tid == 0) {
        double tot = 0.0;
#pragma unroll
        for (int q = 0; q < 4; q++) tot += wres[q];
        atomicAdd(&g_acc, tot);
    }
}

// ---------------------------------------------------------------------------
// Temporal kernel B: per (level,b) — M = 10*max|z|^2 (exact, diagonal),
// sum_x (T-1-x)*(M + log(dg_x + eps)) minus closed-form sum of sims:
//   sum_{y>x} scaled = 10*(|sum_x z_x|^2 - sum_x |z_x|^2)/2.
__global__ void __launch_bounds__(256)
k_tempB(const float* __restrict__ z1, const float* __restrict__ z2) {
    int b = blockIdx.x;
    int l = blockIdx.y;
    int T = TTOP >> l;
    const float* zb = lvl_base(l, b, z1, z2);
    int base = rowOff(l) * 16 + b * T;
    int tid = threadIdx.x;

    __shared__ double sd[256];
    __shared__ float svec[4][64];

    float M = g_M[l * 16 + b];

    float nrmp = 0.f;
    for (int x = tid; x < T; x += 256) nrmp += g_norm[base + x];
    sd[tid] = (double)nrmp;

    {
        int c = tid & 63, rg = tid >> 6;
        float vs = 0.f;
        for (int x = rg; x < T; x += 4) vs += zb[(size_t)x * CDIM + c];
        svec[rg][c] = vs;
    }
    __syncthreads();
    for (int s = 128; s > 0; s >>= 1) {
        if (tid < s) sd[tid] += sd[tid + s];
        __syncthreads();
    }
    double nrmtot = sd[0];
    __syncthreads();

    double s2 = 0.0;
    if (tid < 64) {
        float S = svec[0][tid] + svec[1][tid] + svec[2][tid] + svec[3][tid];
        s2 = (double)S * (double)S;
    }
    sd[tid] = s2;
    __syncthreads();
    for (int s = 128; s > 0; s >>= 1) {
        if (tid < s) sd[tid] += sd[tid + s];
        __syncthreads();
    }
    double S2 = sd[0];
    __syncthreads();

    double sum = 0.0;
    for (int x = tid; x < T; x += 256) {
        float dg = g_row_d[base + x];
        float valrow = M + logf(dg + 1e-5f);
        sum += (double)(T - 1 - x) * (double)valrow;
    }
    sd[tid] = sum;
    __syncthreads();
    for (int s = 128; s > 0; s >>= 1) {
        if (tid < s) sd[tid] += sd[tid + s];
        __syncthreads();
    }
    if (tid == 0) {
        double Ssum = 5.0 * (S2 - nrmtot);
        double wgt = 1.0 / (192.0 * (double)T * (double)(T - 1));
        atomicAdd(&g_acc, wgt * (sd[0] - Ssum));
    }
}

__global__ void k_fin(float* out) { out[0] = (float)g_acc; }

// ---------------------------------------------------------------------------
extern "C" void kernel_launch(void* const* d_in, const int* in_sizes, int n_in,
                              void* d_out, int out_size) {
    const float* z1 = (const float*)d_in[0];
    const float* z2 = (const float*)d_in[1];
    float* out = (float*)d_out;

    {
        int n = 2 * 512 * 2016;
        k_poolA<<<(n + 255) / 256, 256>>>(z1, z2);
    }
    {
        int n = 2 * 512 * 31;
        k_poolB<<<(n + 255) / 256, 256>>>();
    }

    k_norm<<<dim3(16, 11), 256>>>(z1, z2);   // norms, M, zero dg + g_acc
    k_inst<<<1024, 128>>>(z1, z2);
    k_pairs<<<dim3(16, 11), 256>>>(z1, z2);
    k_tempB<<<dim3(16, 11), 256>>>(z1, z2);

    k_fin<<<1, 1>>>(out);
}

// round 12
// speedup vs baseline: 6.8389x; 1.3535x over previous
#include <cuda_runtime.h>
#include <cstdint>
#include <float.h>
#include <math.h>

// ---------------------------------------------------------------------------
// TS2Vec hierarchical loss, B=8, T=2048, C=64, ALPHA=0.5, TAU=0.1, EPS=1e-5
// Round 12: single-pass pooling tree; k_inst bpack eliminated (B-frags are
// components of the A-frag float4); norm+pairs+tempB+fin fused into k_temp
// (per-(l,b) block, all scratch in smem, completion-counter writes output).
// ---------------------------------------------------------------------------

#define TTOP 2048
#define CDIM 64

__device__ double g_acc;
__device__ int g_ctr;
__device__ __align__(16) float g_pyr[2][8 * 2047 * 64];   // pooled levels 1..11

__device__ __forceinline__ int pyrOff(int l) { return 512 * (2048 - (4096 >> l)); }
__device__ __forceinline__ const float* lvl_base(int l, int b,
                                                 const float* z1, const float* z2) {
    int bb = b & 7;
    const float* z = (b < 8) ? z1 : z2;
    const float* p = (b < 8) ? g_pyr[0] : g_pyr[1];
    if (l == 0) return z + (size_t)bb * TTOP * CDIM;
    return p + pyrOff(l) + (size_t)bb * (size_t)(TTOP >> l) * CDIM;
}

__device__ __forceinline__ float tf32r(float x) {
    uint32_t r;
    asm("cvt.rna.tf32.f32 %0, %1;" : "=r"(r) : "f"(x));
    return __uint_as_float(r);
}
__device__ __forceinline__ float4 tf32r4(float4 v) {
    return make_float4(tf32r(v.x), tf32r(v.y), tf32r(v.z), tf32r(v.w));
}

__device__ __forceinline__ void mma_tf32(float c[4], uint32_t a0, uint32_t a1,
                                         uint32_t a2, uint32_t a3,
                                         uint32_t b0, uint32_t b1) {
    asm volatile(
        "mma.sync.aligned.m16n8k8.row.col.f32.tf32.tf32.f32 "
        "{%0,%1,%2,%3}, {%4,%5,%6,%7}, {%8,%9}, {%0,%1,%2,%3};"
        : "+f"(c[0]), "+f"(c[1]), "+f"(c[2]), "+f"(c[3])
        : "r"(a0), "r"(a1), "r"(a2), "r"(a3), "r"(b0), "r"(b1));
}

// ---------------------------------------------------------------------------
// Pool levels 1..6 in ONE pass: thread = (tensor,b,seg,c), 64-row segment,
// binary max tree with carries. Also resets g_acc / g_ctr.
__global__ void __launch_bounds__(256)
k_poolA(const float* __restrict__ z1, const float* __restrict__ z2) {
    int idx = blockIdx.x * 256 + threadIdx.x;       // 0..32767
    if (idx == 0) { g_acc = 0.0; g_ctr = 0; }
    int c = idx & 63;
    int seg = (idx >> 6) & 31;
    int b = (idx >> 11) & 7;
    int tensor = idx >> 14;
    const float* in = tensor ? z2 : z1;
    const float* base = in + ((size_t)b * TTOP + seg * 64) * CDIM + c;
    float* pyr = g_pyr[tensor];

    float c1 = 0.f, c2 = 0.f, c3 = 0.f, c4 = 0.f, c5 = 0.f;
#pragma unroll
    for (int i = 0; i < 32; i++) {
        float a0 = base[(size_t)(2 * i) * CDIM];
        float a1 = base[(size_t)(2 * i + 1) * CDIM];
        float m1 = fmaxf(a0, a1);
        pyr[pyrOff(1) + ((size_t)b * 1024 + seg * 32 + i) * CDIM + c] = m1;
        if (i & 1) {
            float m2 = fmaxf(c1, m1);
            pyr[pyrOff(2) + ((size_t)b * 512 + seg * 16 + (i >> 1)) * CDIM + c] = m2;
            if (i & 2) {
                float m3 = fmaxf(c2, m2);
                pyr[pyrOff(3) + ((size_t)b * 256 + seg * 8 + (i >> 2)) * CDIM + c] = m3;
                if (i & 4) {
                    float m4 = fmaxf(c3, m3);
                    pyr[pyrOff(4) + ((size_t)b * 128 + seg * 4 + (i >> 3)) * CDIM + c] = m4;
                    if (i & 8) {
                        float m5 = fmaxf(c4, m4);
                        pyr[pyrOff(5) + ((size_t)b * 64 + seg * 2 + (i >> 4)) * CDIM + c] = m5;
                        if (i & 16) {
                            float m6 = fmaxf(c5, m5);
                            pyr[pyrOff(6) + ((size_t)b * 32 + seg) * CDIM + c] = m6;
                        } else c5 = m5;
                    } else c4 = m4;
                } else c3 = m3;
            } else c2 = m2;
        } else c1 = m1;
    }
}

// Pool levels 7..11 from level 6 (T6 = 32).
__global__ void k_poolB() {
    int idx = blockIdx.x * blockDim.x + threadIdx.x;
    const int NPER = 512 * 31;
    if (idx >= 2 * NPER) return;
    int tensor = (idx >= NPER) ? 1 : 0;
    int off = idx - tensor * NPER;
    int l = 7, T = 16;
    while (off >= 512 * T) { off -= 512 * T; ++l; T >>= 1; }
    int c = off & 63;
    int t = (off >> 6) % T;
    int b = (off >> 6) / T;
    int w = 32 / T;
    const float* src = g_pyr[tensor] + pyrOff(6) + ((size_t)b * 32 + (size_t)t * w) * CDIM + c;
    float m = src[0];
    for (int k = 1; k < w; k++) m = fmaxf(m, src[(size_t)k * CDIM]);
    g_pyr[tensor][pyrOff(l) + ((size_t)b * T + t) * CDIM + c] = m;
}

// ---------------------------------------------------------------------------
// Instance loss via tf32 mma: one warp per slice, 8 warps/block.
// A pack float4 {A[r][c], A[r+8][c], A[r][c+4], A[r+8][c+4]} also provides the
// B fragments: B(row r) = (x,z), B(row r+8) = (y,w). No separate bpack.
__global__ void __launch_bounds__(256)
k_inst(const float* __restrict__ z1, const float* __restrict__ z2) {
    __shared__ float4 apack[8][8 * 36];
    __shared__ double wres[8];
    int tid = threadIdx.x;
    int w = tid >> 5, lid = tid & 31;
    int gq = lid >> 2, t4 = lid & 3;
    int slice = blockIdx.x * 8 + w;
    double myres = 0.0;

    if (slice < 4095) {
        int l = 0, T = TTOP, tt = slice;
        while (tt >= T) { tt -= T; ++l; T >>= 1; }

#pragma unroll
        for (int i = 0; i < 2; i++) {
            int task = lid + 32 * i;
            int rp = task >> 3, s = task & 7;
            const float* pa = lvl_base(l, rp, z1, z2) + (size_t)tt * CDIM + 8 * s;
            const float* pb = lvl_base(l, rp + 8, z1, z2) + (size_t)tt * CDIM + 8 * s;
            float4 u0 = tf32r4(*reinterpret_cast<const float4*>(pa));
            float4 u1 = tf32r4(*reinterpret_cast<const float4*>(pa + 4));
            float4 v0 = tf32r4(*reinterpret_cast<const float4*>(pb));
            float4 v1 = tf32r4(*reinterpret_cast<const float4*>(pb + 4));
            float4* ap = &apack[w][rp * 36 + s * 4];
            ap[0] = make_float4(u0.x, v0.x, u1.x, v1.x);
            ap[1] = make_float4(u0.y, v0.y, u1.y, v1.y);
            ap[2] = make_float4(u0.z, v0.z, u1.z, v1.z);
            ap[3] = make_float4(u0.w, v0.w, u1.w, v1.w);
        }
        __syncwarp();

        float acc0[4] = {0.f, 0.f, 0.f, 0.f};
        float acc1[4] = {0.f, 0.f, 0.f, 0.f};
#pragma unroll
        for (int s = 0; s < 8; s++) {
            float4 a = apack[w][gq * 36 + s * 4 + t4];
            uint32_t ax = __float_as_uint(a.x), ay = __float_as_uint(a.y);
            uint32_t az = __float_as_uint(a.z), aw = __float_as_uint(a.w);
            mma_tf32(acc0, ax, ay, az, aw, ax, az);   // B rows gq
            mma_tf32(acc1, ax, ay, az, aw, ay, aw);   // B rows gq+8
        }

        int j0 = 2 * t4, j1 = 2 * t4 + 1;
        float vA0 = (j0 == gq) ? -FLT_MAX : acc0[0];
        float vA1 = (j1 == gq) ? -FLT_MAX : acc0[1];
        float vA2 = acc1[0], vA3 = acc1[1];
        float vB0 = acc0[2], vB1 = acc0[3];
        float vB2 = (j0 == gq) ? -FLT_MAX : acc1[2];
        float vB3 = (j1 == gq) ? -FLT_MAX : acc1[3];

        float mA = fmaxf(fmaxf(vA0, vA1), fmaxf(vA2, vA3));
        float mB = fmaxf(fmaxf(vB0, vB1), fmaxf(vB2, vB3));
        mA = fmaxf(mA, __shfl_xor_sync(0xffffffffu, mA, 1));
        mA = fmaxf(mA, __shfl_xor_sync(0xffffffffu, mA, 2));
        mB = fmaxf(mB, __shfl_xor_sync(0xffffffffu, mB, 1));
        mB = fmaxf(mB, __shfl_xor_sync(0xffffffffu, mB, 2));

        float eA = __expf(vA0 - mA) + __expf(vA1 - mA) +
                   __expf(vA2 - mA) + __expf(vA3 - mA);
        float eB = __expf(vB0 - mB) + __expf(vB1 - mB) +
                   __expf(vB2 - mB) + __expf(vB3 - mB);
        eA += __shfl_xor_sync(0xffffffffu, eA, 1);
        eA += __shfl_xor_sync(0xffffffffu, eA, 2);
        eB += __shfl_xor_sync(0xffffffffu, eB, 1);
        eB += __shfl_xor_sync(0xffffffffu, eB, 2);

        float pA = ((j0 == gq) ? acc1[0] : 0.f) + ((j1 == gq) ? acc1[1] : 0.f);
        float pB = ((j0 == gq) ? acc0[2] : 0.f) + ((j1 == gq) ? acc0[3] : 0.f);
        pA += __shfl_xor_sync(0xffffffffu, pA, 1);
        pA += __shfl_xor_sync(0xffffffffu, pA, 2);
        pB += __shfl_xor_sync(0xffffffffu, pB, 1);
        pB += __shfl_xor_sync(0xffffffffu, pB, 2);

        float v = (mA + __logf(eA) - pA) + (mB + __logf(eB) - pB);
        v = (t4 == 0) ? v : 0.f;
#pragma unroll
        for (int o = 16; o > 0; o >>= 1)
            v += __shfl_down_sync(0xffffffffu, v, o);
        if (lid == 0) myres = (double)v / (384.0 * (double)T);
    }
    if (lid == 0) wres[w] = myres;
    __syncthreads();
    if (tid == 0) {
        double tot = 0.0;
#pragma unroll
        for (int q = 0; q < 8; q++) tot += wres[q];
        atomicAdd(&g_acc, tot);
    }
}

// ---------------------------------------------------------------------------
// Fused temporal kernel: per (l,b) block does norms + M + candidate pairs +
// final sums. Last block to finish writes the output (fin folded in).
#define NS 96
#define NSP 97
__global__ void __launch_bounds__(256)
k_temp(const float* __restrict__ z1, const float* __restrict__ z2,
       float* __restrict__ out) {
    int b = blockIdx.x;
    int l = blockIdx.y;
    int T = TTOP >> l;
    const float* zb = lvl_base(l, b, z1, z2);
    int tid = threadIdx.x;

    __shared__ float s_pool[64 * NSP];        // norms (phase 1) / zt stage (phase 3)
    __shared__ float s_dg[2048];
    __shared__ unsigned short s_lst[2048];
    __shared__ float smax[256];
    __shared__ double sd[256];
    __shared__ float svec[4][64];
    __shared__ int s_cnt;

    float* s_nrm = s_pool;                    // first 2048 floats
    if (tid == 0) s_cnt = 0;

    // phase 1: norms, row max, norm sum, column sums
    float mx = 0.f, nrmp = 0.f;
    for (int x = tid; x < T; x += 256) {
        const float4* row = reinterpret_cast<const float4*>(zb + (size_t)x * CDIM);
        float nrm = 0.f;
#pragma unroll
        for (int c = 0; c < 16; c++) {
            float4 v = row[c];
            nrm += v.x * v.x + v.y * v.y + v.z * v.z + v.w * v.w;
        }
        s_nrm[x] = nrm;
        s_dg[x] = 0.f;
        mx = fmaxf(mx, nrm);
        nrmp += nrm;
    }
    smax[tid] = mx;
    sd[tid] = (double)nrmp;
    {
        int c = tid & 63, rg = tid >> 6;
        float vs = 0.f;
        for (int x = rg; x < T; x += 4) vs += zb[(size_t)x * CDIM + c];
        svec[rg][c] = vs;
    }
    __syncthreads();
    for (int s = 128; s > 0; s >>= 1) {
        if (tid < s) {
            smax[tid] = fmaxf(smax[tid], smax[tid + s]);
            sd[tid] += sd[tid + s];
        }
        __syncthreads();
    }
    float M10 = 10.f * smax[0];
    double nrmtot = sd[0];
    __syncthreads();

    double s2 = 0.0;
    if (tid < 64) {
        float S = svec[0][tid] + svec[1][tid] + svec[2][tid] + svec[3][tid];
        s2 = (double)S * (double)S;
    }
    sd[tid] = s2;
    __syncthreads();
    for (int s = 128; s > 0; s >>= 1) {
        if (tid < s) sd[tid] += sd[tid + s];
        __syncthreads();
    }
    double S2 = sd[0];
    __syncthreads();

    // phase 2: Cauchy-Schwarz candidate compaction
    {
        float rhs = M10 - 60.f;
        float thr2 = rhs * rhs;
        for (int x = tid; x < T; x += 256) {
            float nx = s_nrm[x];
            bool skip = (rhs > 0.f) && (10.f * nx * M10 < thr2);
            if (!skip) {
                int p = atomicAdd(&s_cnt, 1);
                s_lst[p] = (unsigned short)x;
            }
        }
    }
    __syncthreads();
    int n = s_cnt;

    if (n >= 2) {
        // phase 3: stage candidate rows transposed (reuses s_pool)
        int nst = (n < NS) ? n : NS;
        __syncthreads();                      // s_nrm dead; safe to overwrite
        for (int e = tid; e < nst * 64; e += 256) {
            int i = e >> 6, k = e & 63;
            s_pool[k * NSP + i] = zb[(size_t)s_lst[i] * CDIM + k];
        }
        __syncthreads();

        // phase 4: candidate pairs -> dg contributions
        for (int i = 0; i < n - 1; i++) {
            int xi = s_lst[i];
            for (int jj = i + 1 + tid; jj < n; jj += 256) {
                int xj = s_lst[jj];
                float acc = 0.f;
                if (i < NS && jj < NS) {
#pragma unroll
                    for (int k = 0; k < 64; k++)
                        acc += s_pool[k * NSP + i] * s_pool[k * NSP + jj];
                } else {
                    const float* pi = zb + (size_t)xi * CDIM;
                    const float* pj = zb + (size_t)xj * CDIM;
#pragma unroll
                    for (int k = 0; k < 64; k++) acc += pi[k] * pj[k];
                }
                float s = 10.f * acc - M10;
                if (s > -70.f) {
                    int xlo = (xi < xj) ? xi : xj;
                    atomicAdd(&s_dg[xlo], __expf(s));
                }
            }
        }
        __syncthreads();
    }

    // phase 5: final weighted sum
    double sum = 0.0;
    for (int x = tid; x < T; x += 256) {
        float valrow = M10 + logf(s_dg[x] + 1e-5f);
        sum += (double)(T - 1 - x) * (double)valrow;
    }
    sd[tid] = sum;
    __syncthreads();
    for (int s = 128; s > 0; s >>= 1) {
        if (tid < s) sd[tid] += sd[tid + s];
        __syncthreads();
    }
    if (tid == 0) {
        double Ssum = 5.0 * (S2 - nrmtot);
        double wgt = 1.0 / (192.0 * (double)T * (double)(T - 1));
        atomicAdd(&g_acc, wgt * (sd[0] - Ssum));
        __threadfence();
        int done = atomicAdd(&g_ctr, 1);
        if (done == 16 * 11 - 1) out[0] = (float)g_acc;
    }
}

// ---------------------------------------------------------------------------
extern "C" void kernel_launch(void* const* d_in, const int* in_sizes, int n_in,
                              void* d_out, int out_size) {
    const float* z1 = (const float*)d_in[0];
    const float* z2 = (const float*)d_in[1];
    float* out = (float*)d_out;

    k_poolA<<<128, 256>>>(z1, z2);            // also resets g_acc / g_ctr
    {
        int n = 2 * 512 * 31;
        k_poolB<<<(n + 255) / 256, 256>>>();
    }
    k_inst<<<512, 256>>>(z1, z2);
    k_temp<<<dim3(16, 11), 256>>>(z1, z2, out);
}

// round 14
// speedup vs baseline: 12.3137x; 1.8005x over previous
#include <cuda_runtime.h>
#include <cstdint>
#include <float.h>
#include <math.h>

// ---------------------------------------------------------------------------
// TS2Vec hierarchical loss, B=8, T=2048, C=64, ALPHA=0.5, TAU=0.1, EPS=1e-5
// Round 14: round-13 k_temp with the divergent-shfl deadlock fixed (uniform
// trip-count phase-1 loop) and s_dg zeroing hoisted out of the n>=2 branch.
// ---------------------------------------------------------------------------

#define TTOP 2048
#define CDIM 64

__device__ double g_acc;
__device__ int g_ctr;
__device__ __align__(16) float g_pyr[2][8 * 2047 * 64];   // pooled levels 1..11

__device__ __forceinline__ int pyrOff(int l) { return 512 * (2048 - (4096 >> l)); }
__device__ __forceinline__ const float* lvl_base(int l, int b,
                                                 const float* z1, const float* z2) {
    int bb = b & 7;
    const float* z = (b < 8) ? z1 : z2;
    const float* p = (b < 8) ? g_pyr[0] : g_pyr[1];
    if (l == 0) return z + (size_t)bb * TTOP * CDIM;
    return p + pyrOff(l) + (size_t)bb * (size_t)(TTOP >> l) * CDIM;
}

__device__ __forceinline__ float tf32r(float x) {
    uint32_t r;
    asm("cvt.rna.tf32.f32 %0, %1;" : "=r"(r) : "f"(x));
    return __uint_as_float(r);
}
__device__ __forceinline__ float4 tf32r4(float4 v) {
    return make_float4(tf32r(v.x), tf32r(v.y), tf32r(v.z), tf32r(v.w));
}

__device__ __forceinline__ void mma_tf32(float c[4], uint32_t a0, uint32_t a1,
                                         uint32_t a2, uint32_t a3,
                                         uint32_t b0, uint32_t b1) {
    asm volatile(
        "mma.sync.aligned.m16n8k8.row.col.f32.tf32.tf32.f32 "
        "{%0,%1,%2,%3}, {%4,%5,%6,%7}, {%8,%9}, {%0,%1,%2,%3};"
        : "+f"(c[0]), "+f"(c[1]), "+f"(c[2]), "+f"(c[3])
        : "r"(a0), "r"(a1), "r"(a2), "r"(a3), "r"(b0), "r"(b1));
}

// ---------------------------------------------------------------------------
// Pool levels 1..6 in ONE pass (binary max tree). Also resets g_acc / g_ctr.
__global__ void __launch_bounds__(256)
k_poolA(const float* __restrict__ z1, const float* __restrict__ z2) {
    int idx = blockIdx.x * 256 + threadIdx.x;       // 0..32767
    if (idx == 0) { g_acc = 0.0; g_ctr = 0; }
    int c = idx & 63;
    int seg = (idx >> 6) & 31;
    int b = (idx >> 11) & 7;
    int tensor = idx >> 14;
    const float* in = tensor ? z2 : z1;
    const float* base = in + ((size_t)b * TTOP + seg * 64) * CDIM + c;
    float* pyr = g_pyr[tensor];

    float c1 = 0.f, c2 = 0.f, c3 = 0.f, c4 = 0.f, c5 = 0.f;
#pragma unroll
    for (int i = 0; i < 32; i++) {
        float a0 = base[(size_t)(2 * i) * CDIM];
        float a1 = base[(size_t)(2 * i + 1) * CDIM];
        float m1 = fmaxf(a0, a1);
        pyr[pyrOff(1) + ((size_t)b * 1024 + seg * 32 + i) * CDIM + c] = m1;
        if (i & 1) {
            float m2 = fmaxf(c1, m1);
            pyr[pyrOff(2) + ((size_t)b * 512 + seg * 16 + (i >> 1)) * CDIM + c] = m2;
            if (i & 2) {
                float m3 = fmaxf(c2, m2);
                pyr[pyrOff(3) + ((size_t)b * 256 + seg * 8 + (i >> 2)) * CDIM + c] = m3;
                if (i & 4) {
                    float m4 = fmaxf(c3, m3);
                    pyr[pyrOff(4) + ((size_t)b * 128 + seg * 4 + (i >> 3)) * CDIM + c] = m4;
                    if (i & 8) {
                        float m5 = fmaxf(c4, m4);
                        pyr[pyrOff(5) + ((size_t)b * 64 + seg * 2 + (i >> 4)) * CDIM + c] = m5;
                        if (i & 16) {
                            float m6 = fmaxf(c5, m5);
                            pyr[pyrOff(6) + ((size_t)b * 32 + seg) * CDIM + c] = m6;
                        } else c5 = m5;
                    } else c4 = m4;
                } else c3 = m3;
            } else c2 = m2;
        } else c1 = m1;
    }
}

// Pool levels 7..11 from level 6 (T6 = 32).
__global__ void k_poolB() {
    int idx = blockIdx.x * blockDim.x + threadIdx.x;
    const int NPER = 512 * 31;
    if (idx >= 2 * NPER) return;
    int tensor = (idx >= NPER) ? 1 : 0;
    int off = idx - tensor * NPER;
    int l = 7, T = 16;
    while (off >= 512 * T) { off -= 512 * T; ++l; T >>= 1; }
    int c = off & 63;
    int t = (off >> 6) % T;
    int b = (off >> 6) / T;
    int w = 32 / T;
    const float* src = g_pyr[tensor] + pyrOff(6) + ((size_t)b * 32 + (size_t)t * w) * CDIM + c;
    float m = src[0];
    for (int k = 1; k < w; k++) m = fmaxf(m, src[(size_t)k * CDIM]);
    g_pyr[tensor][pyrOff(l) + ((size_t)b * T + t) * CDIM + c] = m;
}

// ---------------------------------------------------------------------------
// Instance loss via tf32 mma: one warp per slice, 8 warps/block.
__global__ void __launch_bounds__(256)
k_inst(const float* __restrict__ z1, const float* __restrict__ z2) {
    __shared__ float4 apack[8][8 * 36];
    __shared__ double wres[8];
    int tid = threadIdx.x;
    int w = tid >> 5, lid = tid & 31;
    int gq = lid >> 2, t4 = lid & 3;
    int slice = blockIdx.x * 8 + w;
    double myres = 0.0;

    if (slice < 4095) {
        int l = 0, T = TTOP, tt = slice;
        while (tt >= T) { tt -= T; ++l; T >>= 1; }

#pragma unroll
        for (int i = 0; i < 2; i++) {
            int task = lid + 32 * i;
            int rp = task >> 3, s = task & 7;
            const float* pa = lvl_base(l, rp, z1, z2) + (size_t)tt * CDIM + 8 * s;
            const float* pb = lvl_base(l, rp + 8, z1, z2) + (size_t)tt * CDIM + 8 * s;
            float4 u0 = tf32r4(*reinterpret_cast<const float4*>(pa));
            float4 u1 = tf32r4(*reinterpret_cast<const float4*>(pa + 4));
            float4 v0 = tf32r4(*reinterpret_cast<const float4*>(pb));
            float4 v1 = tf32r4(*reinterpret_cast<const float4*>(pb + 4));
            float4* ap = &apack[w][rp * 36 + s * 4];
            ap[0] = make_float4(u0.x, v0.x, u1.x, v1.x);
            ap[1] = make_float4(u0.y, v0.y, u1.y, v1.y);
            ap[2] = make_float4(u0.z, v0.z, u1.z, v1.z);
            ap[3] = make_float4(u0.w, v0.w, u1.w, v1.w);
        }
        __syncwarp();

        float acc0[4] = {0.f, 0.f, 0.f, 0.f};
        float acc1[4] = {0.f, 0.f, 0.f, 0.f};
#pragma unroll
        for (int s = 0; s < 8; s++) {
            float4 a = apack[w][gq * 36 + s * 4 + t4];
            uint32_t ax = __float_as_uint(a.x), ay = __float_as_uint(a.y);
            uint32_t az = __float_as_uint(a.z), aw = __float_as_uint(a.w);
            mma_tf32(acc0, ax, ay, az, aw, ax, az);   // B rows gq
            mma_tf32(acc1, ax, ay, az, aw, ay, aw);   // B rows gq+8
        }

        int j0 = 2 * t4, j1 = 2 * t4 + 1;
        float vA0 = (j0 == gq) ? -FLT_MAX : acc0[0];
        float vA1 = (j1 == gq) ? -FLT_MAX : acc0[1];
        float vA2 = acc1[0], vA3 = acc1[1];
        float vB0 = acc0[2], vB1 = acc0[3];
        float vB2 = (j0 == gq) ? -FLT_MAX : acc1[2];
        float vB3 = (j1 == gq) ? -FLT_MAX : acc1[3];

        float mA = fmaxf(fmaxf(vA0, vA1), fmaxf(vA2, vA3));
        float mB = fmaxf(fmaxf(vB0, vB1), fmaxf(vB2, vB3));
        mA = fmaxf(mA, __shfl_xor_sync(0xffffffffu, mA, 1));
        mA = fmaxf(mA, __shfl_xor_sync(0xffffffffu, mA, 2));
        mB = fmaxf(mB, __shfl_xor_sync(0xffffffffu, mB, 1));
        mB = fmaxf(mB, __shfl_xor_sync(0xffffffffu, mB, 2));

        float eA = __expf(vA0 - mA) + __expf(vA1 - mA) +
                   __expf(vA2 - mA) + __expf(vA3 - mA);
        float eB = __expf(vB0 - mB) + __expf(vB1 - mB) +
                   __expf(vB2 - mB) + __expf(vB3 - mB);
        eA += __shfl_xor_sync(0xffffffffu, eA, 1);
        eA += __shfl_xor_sync(0xffffffffu, eA, 2);
        eB += __shfl_xor_sync(0xffffffffu, eB, 1);
        eB += __shfl_xor_sync(0xffffffffu, eB, 2);

        float pA = ((j0 == gq) ? acc1[0] : 0.f) + ((j1 == gq) ? acc1[1] : 0.f);
        float pB = ((j0 == gq) ? acc0[2] : 0.f) + ((j1 == gq) ? acc0[3] : 0.f);
        pA += __shfl_xor_sync(0xffffffffu, pA, 1);
        pA += __shfl_xor_sync(0xffffffffu, pA, 2);
        pB += __shfl_xor_sync(0xffffffffu, pB, 1);
        pB += __shfl_xor_sync(0xffffffffu, pB, 2);

        float v = (mA + __logf(eA) - pA) + (mB + __logf(eB) - pB);
        v = (t4 == 0) ? v : 0.f;
#pragma unroll
        for (int o = 16; o > 0; o >>= 1)
            v += __shfl_down_sync(0xffffffffu, v, o);
        if (lid == 0) myres = (double)v / (384.0 * (double)T);
    }
    if (lid == 0) wres[w] = myres;
    __syncthreads();
    if (tid == 0) {
        double tot = 0.0;
#pragma unroll
        for (int q = 0; q < 8; q++) tot += wres[q];
        atomicAdd(&g_acc, tot);
    }
}

// ---------------------------------------------------------------------------
// Fused temporal kernel, 512 threads/block, one block per (l,b).
#define NS 96
#define NSP 97
#define NTH 512
__global__ void __launch_bounds__(NTH)
k_temp(const float* __restrict__ z1, const float* __restrict__ z2,
       float* __restrict__ out) {
    int b = blockIdx.x;
    int l = blockIdx.y;
    int T = TTOP >> l;
    const float* zb = lvl_base(l, b, z1, z2);
    int tid = threadIdx.x;
    int sub = tid & 7, grp = tid >> 3;              // 8 threads per row
    int lane = tid & 31;

    __shared__ float s_pool[64 * NSP];              // s_nrm (2048) / staged zt
    __shared__ float s_dg[2048];
    __shared__ unsigned short s_lst[2048];
    __shared__ float smax[NTH];
    __shared__ double sd[NTH];
    __shared__ float s_svec[64];
    __shared__ int s_cnt;

    float* s_nrm = s_pool;
    if (tid == 0) s_cnt = 0;
    if (tid < 64) s_svec[tid] = 0.f;
    __syncthreads();

    // ---- phase 1: ONE coalesced pass -> row norms, max, norm sum, col sums
    // Uniform trip count (ceil(T/64)) so the intra-warp shfl reductions are
    // executed by EVERY lane every iteration (no divergent collective).
    float cs[8] = {0.f, 0.f, 0.f, 0.f, 0.f, 0.f, 0.f, 0.f};
    float mx = 0.f, nrmp = 0.f;
    int nIter = (T + 63) >> 6;
    for (int it = 0; it < nIter; it++) {
        int x = it * 64 + grp;
        bool act = (x < T);
        float4 a = make_float4(0.f, 0.f, 0.f, 0.f);
        float4 c4v = a;
        if (act) {
            const float4* row = reinterpret_cast<const float4*>(zb + (size_t)x * CDIM);
            a = row[2 * sub];
            c4v = row[2 * sub + 1];
        }
        cs[0] += a.x;   cs[1] += a.y;   cs[2] += a.z;   cs[3] += a.w;
        cs[4] += c4v.x; cs[5] += c4v.y; cs[6] += c4v.z; cs[7] += c4v.w;
        float np = a.x * a.x + a.y * a.y + a.z * a.z + a.w * a.w +
                   c4v.x * c4v.x + c4v.y * c4v.y + c4v.z * c4v.z + c4v.w * c4v.w;
        np += __shfl_xor_sync(0xffffffffu, np, 1);
        np += __shfl_xor_sync(0xffffffffu, np, 2);
        np += __shfl_xor_sync(0xffffffffu, np, 4);
        if (act) {
            if (sub == 0) { s_nrm[x] = np; nrmp += np; }
            mx = fmaxf(mx, np);
        }
    }
    // column sums: combine the 4 row-groups within each warp, then smem atomics
#pragma unroll
    for (int q = 0; q < 8; q++) {
        cs[q] += __shfl_xor_sync(0xffffffffu, cs[q], 8);
        cs[q] += __shfl_xor_sync(0xffffffffu, cs[q], 16);
    }
    if (lane < 8) {
#pragma unroll
        for (int q = 0; q < 8; q++) atomicAdd(&s_svec[8 * lane + q], cs[q]);
    }
    smax[tid] = mx;
    sd[tid] = (double)nrmp;
    __syncthreads();
    for (int s = NTH / 2; s > 0; s >>= 1) {
        if (tid < s) {
            smax[tid] = fmaxf(smax[tid], smax[tid + s]);
            sd[tid] += sd[tid + s];
        }
        __syncthreads();
    }
    float M10 = 10.f * smax[0];
    double nrmtot = sd[0];
    __syncthreads();

    double s2 = 0.0;
    if (tid < 64) {
        float S = s_svec[tid];
        s2 = (double)S * (double)S;
    }
    sd[tid] = s2;
    __syncthreads();
    for (int s = NTH / 2; s > 0; s >>= 1) {
        if (tid < s) sd[tid] += sd[tid + s];
        __syncthreads();
    }
    double S2 = sd[0];
    __syncthreads();

    // ---- phase 2: Cauchy-Schwarz candidate compaction
    {
        float rhs = M10 - 60.f;
        float thr2 = rhs * rhs;
        for (int x = tid; x < T; x += NTH) {
            float nx = s_nrm[x];
            bool skip = (rhs > 0.f) && (10.f * nx * M10 < thr2);
            if (!skip) {
                int p = atomicAdd(&s_cnt, 1);
                s_lst[p] = (unsigned short)x;
            }
        }
    }
    __syncthreads();
    int n = s_cnt;

    // zero dg slots for all candidates (phase 5 reads them for any n)
    for (int i = tid; i < n; i += NTH) s_dg[i] = 0.f;
    __syncthreads();

    if (n >= 2) {
        // ---- phase 3: stage candidate rows transposed (overwrites s_nrm)
        int nst = (n < NS) ? n : NS;
        for (int e = tid; e < nst * 64; e += NTH) {
            int i = e >> 6, k = e & 63;
            s_pool[k * NSP + i] = zb[(size_t)s_lst[i] * CDIM + k];
        }
        __syncthreads();

        // ---- phase 4: flattened candidate-pair loop
        int npairs = n * (n - 1) / 2;
        for (int p = tid; p < npairs; p += NTH) {
            int i = 0, rem = p;
            while (rem >= n - 1 - i) { rem -= n - 1 - i; i++; }
            int j = i + 1 + rem;
            float acc = 0.f;
            if (j < NS) {
#pragma unroll
                for (int k = 0; k < 64; k++)
                    acc += s_pool[k * NSP + i] * s_pool[k * NSP + j];
            } else {
                const float* pi = zb + (size_t)s_lst[i] * CDIM;
                const float* pj = zb + (size_t)s_lst[j] * CDIM;
#pragma unroll
                for (int k = 0; k < 64; k++) acc += pi[k] * pj[k];
            }
            float s = 10.f * acc - M10;
            if (s > -70.f) {
                int pos = (s_lst[i] < s_lst[j]) ? i : j;
                atomicAdd(&s_dg[pos], __expf(s));
            }
        }
        __syncthreads();
    }

    // ---- phase 5: closed-form base + O(n) flagged correction
    float LC = logf(1e-5f);
    float vbase = M10 + LC;
    double sum = (double)vbase * ((double)T * (double)(T - 1) * 0.5);
    double corr = 0.0;
    for (int i = tid; i < n; i += NTH) {
        float dg = s_dg[i];
        if (dg != 0.f) {
            int x = s_lst[i];
            float vr = M10 + logf(dg + 1e-5f);
            corr += (double)(T - 1 - x) * ((double)vr - (double)vbase);
        }
    }
    sd[tid] = corr;
    __syncthreads();
    for (int s = NTH / 2; s > 0; s >>= 1) {
        if (tid < s) sd[tid] += sd[tid + s];
        __syncthreads();
    }
    if (tid == 0) {
        double Ssum = 5.0 * (S2 - nrmtot);
        double wgt = 1.0 / (192.0 * (double)T * (double)(T - 1));
        atomicAdd(&g_acc, wgt * (sum + sd[0] - Ssum));
        __threadfence();
        int done = atomicAdd(&g_ctr, 1);
        if (done == 16 * 11 - 1) out[0] = (float)g_acc;
    }
}

// ---------------------------------------------------------------------------
extern "C" void kernel_launch(void* const* d_in, const int* in_sizes, int n_in,
                              void* d_out, int out_size) {
    const float* z1 = (const float*)d_in[0];
    const float* z2 = (const float*)d_in[1];
    float* out = (float*)d_out;

    k_poolA<<<128, 256>>>(z1, z2);            // also resets g_acc / g_ctr
    {
        int n = 2 * 512 * 31;
        k_poolB<<<(n + 255) / 256, 256>>>();
    }
    k_inst<<<512, 256>>>(z1, z2);
    k_temp<<<dim3(16, 11), NTH>>>(z1, z2, out);
}